// round 1
// baseline (speedup 1.0000x reference)
#include <cuda_runtime.h>
#include <math.h>

// Problem constants
#define B_    2
#define N_    4096
#define C_    256
#define H_    8        // heads
#define D_    32       // head dim
#define M_    1024     // reduced tokens (32x32)
#define HW_   64       // spatial H=W

// ---------------- scratch (device globals; no allocation) ----------------
__device__ float g_q [B_*N_*C_];        // 8 MB : q projection (B*N, C)
__device__ float g_p [B_*M_*C_*4];      // 8 MB : im2col patches (B*M, 4C)
__device__ float g_xs[B_*M_*C_];        // 2 MB : reduced + LN tokens
__device__ float g_kv[B_*M_*2*C_];      // 4 MB : kv projection (B*M, 2C)
__device__ float g_ao[B_*N_*C_];        // 8 MB : attention output

// ---------------- generic tiled GEMM:  C = A * W^T (+bias) ----------------
// A: (Mr x K) row-major, W: (Nc x K) row-major, C: (Mr x Nc) row-major.
// BM=BN=64, BK=16, 256 threads, 4x4 microtile. All dims divisible by 64/16.
__global__ __launch_bounds__(256)
void gemm64(float* __restrict__ Cm, const float* __restrict__ A,
            const float* __restrict__ W, const float* __restrict__ bias,
            int Mr, int Nc, int K) {
    __shared__ float As[64][17];
    __shared__ float Bs[64][17];
    int tid = threadIdx.x;
    int tx = tid & 15, ty = tid >> 4;
    int j0 = blockIdx.x * 64, i0 = blockIdx.y * 64;
    float acc[4][4] = {};
    for (int k0 = 0; k0 < K; k0 += 16) {
#pragma unroll
        for (int r = 0; r < 4; r++) {
            int e = tid + 256 * r;
            int i = e >> 4, k = e & 15;
            As[i][k] = A[(size_t)(i0 + i) * K + k0 + k];
            Bs[i][k] = W[(size_t)(j0 + i) * K + k0 + k];
        }
        __syncthreads();
#pragma unroll
        for (int kk = 0; kk < 16; kk++) {
            float a[4], b[4];
#pragma unroll
            for (int r = 0; r < 4; r++) a[r] = As[ty * 4 + r][kk];
#pragma unroll
            for (int c = 0; c < 4; c++) b[c] = Bs[tx * 4 + c][kk];
#pragma unroll
            for (int r = 0; r < 4; r++)
#pragma unroll
                for (int c = 0; c < 4; c++) acc[r][c] += a[r] * b[c];
        }
        __syncthreads();
    }
#pragma unroll
    for (int r = 0; r < 4; r++)
#pragma unroll
        for (int c = 0; c < 4; c++) {
            int j = j0 + tx * 4 + c;
            float v = acc[r][c];
            if (bias) v += bias[j];
            Cm[(size_t)(i0 + ty * 4 + r) * Nc + j] = v;
        }
}

// ---------------- im2col for 2x2 stride-2 conv (OIHW weights) ----------------
// P[row = b*M+m][k = cin*4 + kh*2 + kw] = x[b][(2i+kh)*64 + 2j+kw][cin]
__global__ __launch_bounds__(256)
void im2col_k(float* __restrict__ P, const float* __restrict__ x) {
    int idx = blockIdx.x * blockDim.x + threadIdx.x;   // over (B*M) * C
    if (idx >= B_ * M_ * C_) return;
    int cin = idx & (C_ - 1);
    int row = idx >> 8;          // b*M + m
    int b   = row >> 10;
    int m   = row & (M_ - 1);
    int i = m >> 5, j = m & 31;
    const float* xb = x + (size_t)b * N_ * C_;
    float* pr = P + (size_t)row * (4 * C_) + cin * 4;
#pragma unroll
    for (int kh = 0; kh < 2; kh++)
#pragma unroll
        for (int kw = 0; kw < 2; kw++) {
            int n = (2 * i + kh) * HW_ + (2 * j + kw);
            pr[kh * 2 + kw] = xb[(size_t)n * C_ + cin];
        }
}

// ---------------- LayerNorm over C=256, one block per row ----------------
__global__ __launch_bounds__(256)
void layernorm_k(float* __restrict__ xs, const float* __restrict__ w,
                 const float* __restrict__ bvec) {
    int row = blockIdx.x;
    int tid = threadIdx.x;
    float v = xs[(size_t)row * C_ + tid];
    float s = v, s2 = v * v;
#pragma unroll
    for (int o = 16; o > 0; o >>= 1) {
        s  += __shfl_xor_sync(~0u, s,  o);
        s2 += __shfl_xor_sync(~0u, s2, o);
    }
    __shared__ float rs[8], rs2[8];
    int wid = tid >> 5, lane = tid & 31;
    if (lane == 0) { rs[wid] = s; rs2[wid] = s2; }
    __syncthreads();
    float tot = 0.f, tot2 = 0.f;
#pragma unroll
    for (int i = 0; i < 8; i++) { tot += rs[i]; tot2 += rs2[i]; }
    float mu  = tot * (1.f / C_);
    float var = tot2 * (1.f / C_) - mu * mu;
    float inv = rsqrtf(var + 1e-5f);
    xs[(size_t)row * C_ + tid] = (v - mu) * inv * w[tid] + bvec[tid];
}

// ---------------- fused flash-style attention ----------------
// grid: (64 row-tiles, 16 = b*8+h), block 256.
// Each block: 64 q rows x full M=1024 kv, online softmax, d=32.
__global__ __launch_bounds__(256)
void attention_k(float* __restrict__ ao, const float* __restrict__ q,
                 const float* __restrict__ kv) {
    __shared__ float qs[64][33];
    __shared__ float ks[64][33];
    __shared__ float vs[64][33];
    __shared__ float Ss[64][65];
    int tid = threadIdx.x;
    int bh = blockIdx.y;
    int b = bh >> 3, h = bh & 7;
    int r0 = blockIdx.x * 64;
    int row = tid >> 2;      // 0..63 (4 threads per row, same warp)
    int seg = tid & 3;       // 0..3

    const float* qg = q + (size_t)b * N_ * C_ + (size_t)r0 * C_ + h * D_;
    for (int e = tid; e < 64 * 32; e += 256) {
        int i = e >> 5, d = e & 31;
        qs[i][d] = qg[(size_t)i * C_ + d];
    }
    __syncthreads();
    float qr[32];
#pragma unroll
    for (int d = 0; d < 32; d++) qr[d] = qs[row][d];

    float mrow = -1e30f, lrow = 0.f;
    float O[8] = {};
    const float scale = 0.17677669529663687f;  // 32^-0.5
    const float* kg = kv + (size_t)b * M_ * (2 * C_) + h * D_;

    for (int j0 = 0; j0 < M_; j0 += 64) {
        __syncthreads();
        for (int e = tid; e < 64 * 32; e += 256) {
            int jj = e >> 5, d = e & 31;
            const float* krow = kg + (size_t)(j0 + jj) * (2 * C_);
            ks[jj][d] = krow[d];
            vs[jj][d] = krow[C_ + d];
        }
        __syncthreads();

        float sr[16];
        float cmax = -1e30f;
#pragma unroll
        for (int jj = 0; jj < 16; jj++) {
            int j = seg * 16 + jj;
            float s = 0.f;
#pragma unroll
            for (int d = 0; d < 32; d++) s += qr[d] * ks[j][d];
            s *= scale;
            sr[jj] = s;
            cmax = fmaxf(cmax, s);
        }
        cmax = fmaxf(cmax, __shfl_xor_sync(~0u, cmax, 1));
        cmax = fmaxf(cmax, __shfl_xor_sync(~0u, cmax, 2));
        float nm = fmaxf(mrow, cmax);
        float corr = __expf(mrow - nm);
        float ps = 0.f;
#pragma unroll
        for (int jj = 0; jj < 16; jj++) {
            float p = __expf(sr[jj] - nm);
            Ss[row][seg * 16 + jj] = p;
            ps += p;
        }
        ps += __shfl_xor_sync(~0u, ps, 1);
        ps += __shfl_xor_sync(~0u, ps, 2);
        lrow = lrow * corr + ps;
        mrow = nm;
#pragma unroll
        for (int c = 0; c < 8; c++) O[c] *= corr;
        __syncwarp();   // Ss row is produced/consumed by the same 4 lanes' warp
#pragma unroll 4
        for (int j = 0; j < 64; j++) {
            float p = Ss[row][j];
#pragma unroll
            for (int c = 0; c < 8; c++) O[c] += p * vs[j][seg * 8 + c];
        }
    }
    float inv = 1.f / lrow;
    float* og = ao + (size_t)b * N_ * C_ + (size_t)(r0 + row) * C_ + h * D_ + seg * 8;
#pragma unroll
    for (int c = 0; c < 8; c++) og[c] = O[c] * inv;
}

// ---------------- launch ----------------
extern "C" void kernel_launch(void* const* d_in, const int* in_sizes, int n_in,
                              void* d_out, int out_size) {
    const float* x[2]   = {(const float*)d_in[0], (const float*)d_in[1]};
    const float* Wq     = (const float*)d_in[2];
    const float* Wkv    = (const float*)d_in[3];
    const float* Wproj  = (const float*)d_in[4];
    const float* bproj  = (const float*)d_in[5];
    const float* Wsr    = (const float*)d_in[6];
    const float* bsr    = (const float*)d_in[7];
    const float* lnw[2] = {(const float*)d_in[8],  (const float*)d_in[10]};
    const float* lnb[2] = {(const float*)d_in[9],  (const float*)d_in[11]};
    float* out = (float*)d_out;

    float *q, *p, *xs, *kvb, *ao;
    cudaGetSymbolAddress((void**)&q,   g_q);
    cudaGetSymbolAddress((void**)&p,   g_p);
    cudaGetSymbolAddress((void**)&xs,  g_xs);
    cudaGetSymbolAddress((void**)&kvb, g_kv);
    cudaGetSymbolAddress((void**)&ao,  g_ao);

    for (int s = 0; s < 2; s++) {
        // q = x @ Wq^T                         (8192 x 256 x 256)
        gemm64<<<dim3(C_ / 64, (B_ * N_) / 64), 256>>>(q, x[s], Wq, nullptr,
                                                       B_ * N_, C_, C_);
        // im2col patches
        im2col_k<<<(B_ * M_ * C_ + 255) / 256, 256>>>(p, x[s]);
        // xs = patches @ Wsr^T + bsr           (2048 x 256 x 1024)
        gemm64<<<dim3(C_ / 64, (B_ * M_) / 64), 256>>>(xs, p, Wsr, bsr,
                                                       B_ * M_, C_, 4 * C_);
        // layernorm (in place)
        layernorm_k<<<B_ * M_, 256>>>(xs, lnw[s], lnb[s]);
        // kv = xs @ Wkv^T                      (2048 x 512 x 256)
        gemm64<<<dim3((2 * C_) / 64, (B_ * M_) / 64), 256>>>(kvb, xs, Wkv, nullptr,
                                                             B_ * M_, 2 * C_, C_);
        // fused attention
        attention_k<<<dim3(N_ / 64, B_ * H_), 256>>>(ao, q, kvb);
        // y = ao @ Wproj^T + bproj
        gemm64<<<dim3(C_ / 64, (B_ * N_) / 64), 256>>>(out + (size_t)s * B_ * N_ * C_,
                                                       ao, Wproj, bproj,
                                                       B_ * N_, C_, C_);
    }
}

// round 2
// speedup vs baseline: 2.2734x; 2.2734x over previous
#include <cuda_runtime.h>
#include <math.h>

// Problem constants
#define B_    2
#define N_    4096
#define C_    256
#define H_    8        // heads
#define D_    32       // head dim
#define M_    1024     // reduced tokens (32x32)
#define HW_   64       // spatial H=W

// ---------------- scratch (device globals; both streams) ----------------
__device__ float g_q [2*B_*N_*C_];        // 16 MB : q projection
__device__ float g_p [2*B_*M_*C_*4];      // 16 MB : im2col patches
__device__ float g_xs[2*B_*M_*C_];        //  4 MB : reduced + LN tokens
__device__ float g_kv[2*B_*M_*2*C_];      //  8 MB : kv projection
__device__ float g_ao[2*B_*N_*C_];        // 16 MB : attention output

// ---------------- GEMM:  out = A * W^T (+bias) ----------------
// A: (Mr x K) row-major, W: (Nc x K) row-major, out: (Mr x Nc) row-major.
// Tile 128x64, BK=16, 256 threads, 8x4 microtile, k-major smem (vector reads).
// blockIdx.z selects stream (out/A pointer pair). K % 16 == 0, K/4 aligned.
__global__ __launch_bounds__(256)
void gemm128(float* __restrict__ out0, float* __restrict__ out1,
             const float* __restrict__ A0, const float* __restrict__ A1,
             const float* __restrict__ W, const float* __restrict__ bias,
             int Nc, int K) {
    __shared__ float As[16][132];   // [k][i], stride 132 (16B-aligned rows)
    __shared__ float Bs[16][68];    // [k][j]
    const int z = blockIdx.z;
    const float* A = z ? A1 : A0;
    float* out = z ? out1 : out0;
    const int tid = threadIdx.x;
    const int tx = tid & 15, ty = tid >> 4;
    const int i0 = blockIdx.y * 128, j0 = blockIdx.x * 64;
    float acc[8][4] = {};

    for (int k0 = 0; k0 < K; k0 += 16) {
        // load A tile (128 x 16) -> transposed smem: 512 float4
#pragma unroll
        for (int r = 0; r < 2; r++) {
            int f = tid + 256 * r;
            int row = f >> 2, kq = (f & 3) << 2;
            float4 v = *(const float4*)&A[(size_t)(i0 + row) * K + k0 + kq];
            As[kq + 0][row] = v.x; As[kq + 1][row] = v.y;
            As[kq + 2][row] = v.z; As[kq + 3][row] = v.w;
        }
        // load W tile (64 x 16): 256 float4
        {
            int row = tid >> 2, kq = (tid & 3) << 2;
            float4 v = *(const float4*)&W[(size_t)(j0 + row) * K + k0 + kq];
            Bs[kq + 0][row] = v.x; Bs[kq + 1][row] = v.y;
            Bs[kq + 2][row] = v.z; Bs[kq + 3][row] = v.w;
        }
        __syncthreads();
#pragma unroll
        for (int kk = 0; kk < 16; kk++) {
            float4 a0 = *(const float4*)&As[kk][ty * 8];
            float4 a1 = *(const float4*)&As[kk][ty * 8 + 4];
            float4 bv = *(const float4*)&Bs[kk][tx * 4];
            float a[8] = {a0.x, a0.y, a0.z, a0.w, a1.x, a1.y, a1.z, a1.w};
            float b[4] = {bv.x, bv.y, bv.z, bv.w};
#pragma unroll
            for (int r = 0; r < 8; r++)
#pragma unroll
                for (int c = 0; c < 4; c++) acc[r][c] += a[r] * b[c];
        }
        __syncthreads();
    }
    float4 bb = make_float4(0.f, 0.f, 0.f, 0.f);
    if (bias) bb = *(const float4*)&bias[j0 + tx * 4];
#pragma unroll
    for (int r = 0; r < 8; r++) {
        float4 v = make_float4(acc[r][0] + bb.x, acc[r][1] + bb.y,
                               acc[r][2] + bb.z, acc[r][3] + bb.w);
        *(float4*)&out[(size_t)(i0 + ty * 8 + r) * Nc + j0 + tx * 4] = v;
    }
}

// ---------------- im2col for 2x2 stride-2 conv (OIHW weights) ----------------
__global__ __launch_bounds__(256)
void im2col_k(float* __restrict__ Pb, const float* __restrict__ x0,
              const float* __restrict__ x1) {
    int idx = blockIdx.x * blockDim.x + threadIdx.x;   // over (B*M) * C
    if (idx >= B_ * M_ * C_) return;
    int z = blockIdx.y;
    const float* x = z ? x1 : x0;
    float* P = Pb + (size_t)z * B_ * M_ * 4 * C_;
    int cin = idx & (C_ - 1);
    int row = idx >> 8;          // b*M + m
    int b   = row >> 10;
    int m   = row & (M_ - 1);
    int i = m >> 5, j = m & 31;
    const float* xb = x + (size_t)b * N_ * C_;
    float* pr = P + (size_t)row * (4 * C_) + cin * 4;
#pragma unroll
    for (int kh = 0; kh < 2; kh++)
#pragma unroll
        for (int kw = 0; kw < 2; kw++) {
            int n = (2 * i + kh) * HW_ + (2 * j + kw);
            pr[kh * 2 + kw] = xb[(size_t)n * C_ + cin];
        }
}

// ---------------- LayerNorm over C=256, one block per row ----------------
__global__ __launch_bounds__(256)
void layernorm_k(float* __restrict__ xsb,
                 const float* __restrict__ w0, const float* __restrict__ b0,
                 const float* __restrict__ w1, const float* __restrict__ b1) {
    int z = blockIdx.y;
    float* xs = xsb + (size_t)z * B_ * M_ * C_;
    const float* w = z ? w1 : w0;
    const float* bv = z ? b1 : b0;
    int row = blockIdx.x;
    int tid = threadIdx.x;
    float v = xs[(size_t)row * C_ + tid];
    float s = v, s2 = v * v;
#pragma unroll
    for (int o = 16; o > 0; o >>= 1) {
        s  += __shfl_xor_sync(~0u, s,  o);
        s2 += __shfl_xor_sync(~0u, s2, o);
    }
    __shared__ float rs[8], rs2[8];
    int wid = tid >> 5, lane = tid & 31;
    if (lane == 0) { rs[wid] = s; rs2[wid] = s2; }
    __syncthreads();
    float tot = 0.f, tot2 = 0.f;
#pragma unroll
    for (int i = 0; i < 8; i++) { tot += rs[i]; tot2 += rs2[i]; }
    float mu  = tot * (1.f / C_);
    float var = tot2 * (1.f / C_) - mu * mu;
    float inv = rsqrtf(var + 1e-5f);
    xs[(size_t)row * C_ + tid] = (v - mu) * inv * w[tid] + bv[tid];
}

// ---------------- fused flash-style attention ----------------
// grid: (64 row-tiles, 16 = b*8+h, 2 streams), block 256 (16x16 thread grid).
// Each block: 64 q rows x full M=1024 kv in 64-chunks; 4x4 S tile, 4x2 O tile.
__global__ __launch_bounds__(256)
void attention_k(float* __restrict__ aoB, const float* __restrict__ qB,
                 const float* __restrict__ kvB) {
    __shared__ float qsT[32][68];   // [d][i]
    __shared__ float ksT[32][68];   // [d][j]
    __shared__ float vs[64][36];    // [j][d]
    __shared__ float Ps[64][68];    // [j][i]
    const int z = blockIdx.z;
    const float* q  = qB  + (size_t)z * B_ * N_ * C_;
    const float* kv = kvB + (size_t)z * B_ * M_ * 2 * C_;
    float* ao = aoB + (size_t)z * B_ * N_ * C_;
    const int tid = threadIdx.x;
    const int tx = tid & 15, ty = tid >> 4;
    const int bh = blockIdx.y;
    const int b = bh >> 3, h = bh & 7;
    const int r0 = blockIdx.x * 64;
    const float scale = 0.17677669529663687f;  // 32^-0.5

    const float* qg = q + ((size_t)b * N_ + r0) * C_ + h * D_;
    for (int e = tid; e < 64 * 32; e += 256) {
        int i = e >> 5, d = e & 31;
        qsT[d][i] = qg[(size_t)i * C_ + d] * scale;
    }

    float m[4], l[4], O[4][2];
#pragma unroll
    for (int r = 0; r < 4; r++) {
        m[r] = -1e30f; l[r] = 0.f; O[r][0] = 0.f; O[r][1] = 0.f;
    }
    const float* kg = kv + (size_t)b * M_ * (2 * C_) + h * D_;

    for (int j0 = 0; j0 < M_; j0 += 64) {
        __syncthreads();   // prior PV done before overwriting ks/vs
        for (int e = tid; e < 64 * 32; e += 256) {
            int j = e >> 5, d = e & 31;
            const float* kr = kg + (size_t)(j0 + j) * (2 * C_);
            ksT[d][j] = kr[d];
            vs[j][d]  = kr[C_ + d];
        }
        __syncthreads();

        // S = q k^T (pre-scaled), 4x4 register tile
        float S[4][4] = {};
#pragma unroll
        for (int d = 0; d < 32; d++) {
            float4 av = *(const float4*)&qsT[d][ty * 4];
            float4 bv = *(const float4*)&ksT[d][tx * 4];
            float a[4] = {av.x, av.y, av.z, av.w};
            float bq[4] = {bv.x, bv.y, bv.z, bv.w};
#pragma unroll
            for (int r = 0; r < 4; r++)
#pragma unroll
                for (int c = 0; c < 4; c++) S[r][c] += a[r] * bq[c];
        }
        // online softmax per row (row stats across the 16 tx lanes)
#pragma unroll
        for (int r = 0; r < 4; r++) {
            float cm = fmaxf(fmaxf(S[r][0], S[r][1]), fmaxf(S[r][2], S[r][3]));
            cm = fmaxf(cm, __shfl_xor_sync(~0u, cm, 1));
            cm = fmaxf(cm, __shfl_xor_sync(~0u, cm, 2));
            cm = fmaxf(cm, __shfl_xor_sync(~0u, cm, 4));
            cm = fmaxf(cm, __shfl_xor_sync(~0u, cm, 8));
            float nm = fmaxf(m[r], cm);
            float corr = __expf(m[r] - nm);
            m[r] = nm;
            float ps = 0.f;
#pragma unroll
            for (int c = 0; c < 4; c++) {
                float p = __expf(S[r][c] - nm);
                Ps[tx * 4 + c][ty * 4 + r] = p;
                ps += p;
            }
            ps += __shfl_xor_sync(~0u, ps, 1);
            ps += __shfl_xor_sync(~0u, ps, 2);
            ps += __shfl_xor_sync(~0u, ps, 4);
            ps += __shfl_xor_sync(~0u, ps, 8);
            l[r] = l[r] * corr + ps;
            O[r][0] *= corr; O[r][1] *= corr;
        }
        __syncthreads();   // Ps fully written before PV reads across tx groups

        // O += P V  (4 rows x 2 d-cols per thread)
#pragma unroll 8
        for (int j = 0; j < 64; j++) {
            float4 pv = *(const float4*)&Ps[j][ty * 4];
            float2 vv = *(const float2*)&vs[j][tx * 2];
            float p[4] = {pv.x, pv.y, pv.z, pv.w};
#pragma unroll
            for (int r = 0; r < 4; r++) {
                O[r][0] += p[r] * vv.x;
                O[r][1] += p[r] * vv.y;
            }
        }
    }
    float* og = ao + ((size_t)b * N_ + r0) * C_ + h * D_;
#pragma unroll
    for (int r = 0; r < 4; r++) {
        int row = ty * 4 + r;
        float inv = 1.f / l[r];
        og[(size_t)row * C_ + tx * 2 + 0] = O[r][0] * inv;
        og[(size_t)row * C_ + tx * 2 + 1] = O[r][1] * inv;
    }
}

// ---------------- launch ----------------
extern "C" void kernel_launch(void* const* d_in, const int* in_sizes, int n_in,
                              void* d_out, int out_size) {
    const float* x0     = (const float*)d_in[0];
    const float* x1     = (const float*)d_in[1];
    const float* Wq     = (const float*)d_in[2];
    const float* Wkv    = (const float*)d_in[3];
    const float* Wproj  = (const float*)d_in[4];
    const float* bproj  = (const float*)d_in[5];
    const float* Wsr    = (const float*)d_in[6];
    const float* bsr    = (const float*)d_in[7];
    const float* lnw0   = (const float*)d_in[8];
    const float* lnb0   = (const float*)d_in[9];
    const float* lnw1   = (const float*)d_in[10];
    const float* lnb1   = (const float*)d_in[11];
    float* out = (float*)d_out;

    float *q, *p, *xs, *kvb, *ao;
    cudaGetSymbolAddress((void**)&q,   g_q);
    cudaGetSymbolAddress((void**)&p,   g_p);
    cudaGetSymbolAddress((void**)&xs,  g_xs);
    cudaGetSymbolAddress((void**)&kvb, g_kv);
    cudaGetSymbolAddress((void**)&ao,  g_ao);

    const size_t sQ  = (size_t)B_ * N_ * C_;       // per-stream q/ao elements
    const size_t sP  = (size_t)B_ * M_ * 4 * C_;
    const size_t sXS = (size_t)B_ * M_ * C_;
    const size_t sKV = (size_t)B_ * M_ * 2 * C_;

    // q = x @ Wq^T              (8192 x 256, K=256) both streams
    gemm128<<<dim3(C_ / 64, (B_ * N_) / 128, 2), 256>>>(
        q, q + sQ, x0, x1, Wq, nullptr, C_, C_);
    // im2col patches, both streams
    im2col_k<<<dim3((B_ * M_ * C_ + 255) / 256, 2), 256>>>(p, x0, x1);
    // xs = patches @ Wsr^T + bsr  (2048 x 256, K=1024)
    gemm128<<<dim3(C_ / 64, (B_ * M_) / 128, 2), 256>>>(
        xs, xs + sXS, p, p + sP, Wsr, bsr, C_, 4 * C_);
    // layernorm (in place), per-stream weights
    layernorm_k<<<dim3(B_ * M_, 2), 256>>>(xs, lnw0, lnb0, lnw1, lnb1);
    // kv = xs @ Wkv^T            (2048 x 512, K=256)
    gemm128<<<dim3((2 * C_) / 64, (B_ * M_) / 128, 2), 256>>>(
        kvb, kvb + sKV, xs, xs + sXS, Wkv, nullptr, 2 * C_, C_);
    // fused attention
    attention_k<<<dim3(N_ / 64, B_ * H_, 2), 256>>>(ao, q, kvb);
    // y = ao @ Wproj^T + bproj
    gemm128<<<dim3(C_ / 64, (B_ * N_) / 128, 2), 256>>>(
        out, out + sQ, ao, ao + sQ, Wproj, bproj, C_, C_);
}

// round 3
// speedup vs baseline: 2.6985x; 1.1870x over previous
#include <cuda_runtime.h>
#include <math.h>

// Problem constants
#define B_    2
#define N_    4096
#define C_    256
#define H_    8        // heads
#define D_    32       // head dim
#define M_    1024     // reduced tokens (32x32)
#define HW_   64       // spatial H=W

typedef unsigned long long u64;

// ---------------- packed f32x2 helpers (sm_103a FFMA2 path) ----------------
__device__ __forceinline__ u64 pk2(float lo, float hi) {
    u64 r; asm("mov.b64 %0, {%1, %2};" : "=l"(r) : "f"(lo), "f"(hi)); return r;
}
__device__ __forceinline__ float2 up2(u64 p) {
    float2 f; asm("mov.b64 {%0, %1}, %2;" : "=f"(f.x), "=f"(f.y) : "l"(p)); return f;
}
__device__ __forceinline__ void fma2(u64& d, u64 a, u64 b) {
    asm("fma.rn.f32x2 %0, %1, %2, %0;" : "+l"(d) : "l"(a), "l"(b));
}
__device__ __forceinline__ void mul2(u64& d, u64 a) {
    asm("mul.rn.f32x2 %0, %0, %1;" : "+l"(d) : "l"(a));
}

// ---------------- scratch (device globals; both streams) ----------------
__device__ float g_q [2*B_*N_*C_];        // 16 MB : q projection
__device__ float g_p [2*B_*M_*C_*4];      // 16 MB : im2col patches
__device__ float g_xs[2*B_*M_*C_];        //  4 MB : reduced + LN tokens
__device__ float g_kv[2*B_*M_*2*C_];      //  8 MB : kv projection
__device__ float g_ao[2*B_*N_*C_];        // 16 MB : attention output

// ---------------- GEMM:  out = A * W^T (+bias) ----------------
// Tile 128x64, BK=16, 256 threads, 8x4 microtile as 4 row-pairs (f32x2).
__global__ __launch_bounds__(256)
void gemm128(float* __restrict__ out0, float* __restrict__ out1,
             const float* __restrict__ A0, const float* __restrict__ A1,
             const float* __restrict__ W, const float* __restrict__ bias,
             int Nc, int K) {
    __shared__ float As[16][132];   // [k][i]
    __shared__ float Bs[16][68];    // [k][j]
    const int z = blockIdx.z;
    const float* A = z ? A1 : A0;
    float* out = z ? out1 : out0;
    const int tid = threadIdx.x;
    const int tx = tid & 15, ty = tid >> 4;
    const int i0 = blockIdx.y * 128, j0 = blockIdx.x * 64;
    u64 acc2[4][4] = {};            // row-pairs x 4 cols

    for (int k0 = 0; k0 < K; k0 += 16) {
#pragma unroll
        for (int r = 0; r < 2; r++) {
            int f = tid + 256 * r;
            int row = f >> 2, kq = (f & 3) << 2;
            float4 v = *(const float4*)&A[(size_t)(i0 + row) * K + k0 + kq];
            As[kq + 0][row] = v.x; As[kq + 1][row] = v.y;
            As[kq + 2][row] = v.z; As[kq + 3][row] = v.w;
        }
        {
            int row = tid >> 2, kq = (tid & 3) << 2;
            float4 v = *(const float4*)&W[(size_t)(j0 + row) * K + k0 + kq];
            Bs[kq + 0][row] = v.x; Bs[kq + 1][row] = v.y;
            Bs[kq + 2][row] = v.z; Bs[kq + 3][row] = v.w;
        }
        __syncthreads();
#pragma unroll
        for (int kk = 0; kk < 16; kk++) {
            ulonglong2 aA = *(const ulonglong2*)&As[kk][ty * 8];
            ulonglong2 aB = *(const ulonglong2*)&As[kk][ty * 8 + 4];
            float4 bv = *(const float4*)&Bs[kk][tx * 4];
            u64 ap[4] = {aA.x, aA.y, aB.x, aB.y};
            u64 bp[4] = {pk2(bv.x, bv.x), pk2(bv.y, bv.y),
                         pk2(bv.z, bv.z), pk2(bv.w, bv.w)};
#pragma unroll
            for (int r = 0; r < 4; r++)
#pragma unroll
                for (int c = 0; c < 4; c++) fma2(acc2[r][c], ap[r], bp[c]);
        }
        __syncthreads();
    }
    float4 bb = make_float4(0.f, 0.f, 0.f, 0.f);
    if (bias) bb = *(const float4*)&bias[j0 + tx * 4];
#pragma unroll
    for (int p = 0; p < 4; p++) {
        float2 c0 = up2(acc2[p][0]), c1 = up2(acc2[p][1]);
        float2 c2 = up2(acc2[p][2]), c3 = up2(acc2[p][3]);
        size_t r0 = (size_t)(i0 + ty * 8 + 2 * p) * Nc + j0 + tx * 4;
        *(float4*)&out[r0]      = make_float4(c0.x + bb.x, c1.x + bb.y,
                                              c2.x + bb.z, c3.x + bb.w);
        *(float4*)&out[r0 + Nc] = make_float4(c0.y + bb.x, c1.y + bb.y,
                                              c2.y + bb.z, c3.y + bb.w);
    }
}

// ---------------- im2col for 2x2 stride-2 conv ----------------
__global__ __launch_bounds__(256)
void im2col_k(float* __restrict__ Pb, const float* __restrict__ x0,
              const float* __restrict__ x1) {
    int idx = blockIdx.x * blockDim.x + threadIdx.x;
    if (idx >= B_ * M_ * C_) return;
    int z = blockIdx.y;
    const float* x = z ? x1 : x0;
    float* P = Pb + (size_t)z * B_ * M_ * 4 * C_;
    int cin = idx & (C_ - 1);
    int row = idx >> 8;
    int b   = row >> 10;
    int m   = row & (M_ - 1);
    int i = m >> 5, j = m & 31;
    const float* xb = x + (size_t)b * N_ * C_;
    float* pr = P + (size_t)row * (4 * C_) + cin * 4;
#pragma unroll
    for (int kh = 0; kh < 2; kh++)
#pragma unroll
        for (int kw = 0; kw < 2; kw++) {
            int n = (2 * i + kh) * HW_ + (2 * j + kw);
            pr[kh * 2 + kw] = xb[(size_t)n * C_ + cin];
        }
}

// ---------------- LayerNorm over C=256 ----------------
__global__ __launch_bounds__(256)
void layernorm_k(float* __restrict__ xsb,
                 const float* __restrict__ w0, const float* __restrict__ b0,
                 const float* __restrict__ w1, const float* __restrict__ b1) {
    int z = blockIdx.y;
    float* xs = xsb + (size_t)z * B_ * M_ * C_;
    const float* w = z ? w1 : w0;
    const float* bv = z ? b1 : b0;
    int row = blockIdx.x;
    int tid = threadIdx.x;
    float v = xs[(size_t)row * C_ + tid];
    float s = v, s2 = v * v;
#pragma unroll
    for (int o = 16; o > 0; o >>= 1) {
        s  += __shfl_xor_sync(~0u, s,  o);
        s2 += __shfl_xor_sync(~0u, s2, o);
    }
    __shared__ float rs[8], rs2[8];
    int wid = tid >> 5, lane = tid & 31;
    if (lane == 0) { rs[wid] = s; rs2[wid] = s2; }
    __syncthreads();
    float tot = 0.f, tot2 = 0.f;
#pragma unroll
    for (int i = 0; i < 8; i++) { tot += rs[i]; tot2 += rs2[i]; }
    float mu  = tot * (1.f / C_);
    float var = tot2 * (1.f / C_) - mu * mu;
    float inv = rsqrtf(var + 1e-5f);
    xs[(size_t)row * C_ + tid] = (v - mu) * inv * w[tid] + bv[tid];
}

// ---------------- fused flash-style attention (f32x2) ----------------
// grid: (N/128, b*h=16, 2 streams), 256 threads (16x16).
// Block: 128 q rows x M=1024 kv in 64-chunks. S microtile 8x4 (4 row-pairs),
// O microtile 8x2 (4 row-pairs).
#define QROWS 128
__global__ __launch_bounds__(256)
void attention_k(float* __restrict__ aoB, const float* __restrict__ qB,
                 const float* __restrict__ kvB) {
    extern __shared__ float sm[];
    float (*qsT)[132] = (float(*)[132])sm;                              // [d][i] 32x132
    float (*ksT)[68]  = (float(*)[68])(sm + 32 * 132);                  // [d][j] 32x68
    float (*vs)[36]   = (float(*)[36])(sm + 32 * 132 + 32 * 68);        // [j][d] 64x36
    float (*Ps)[132]  = (float(*)[132])(sm + 32 * 132 + 32 * 68 + 64 * 36); // [j][i]

    const int z = blockIdx.z;
    const float* q  = qB  + (size_t)z * B_ * N_ * C_;
    const float* kv = kvB + (size_t)z * B_ * M_ * 2 * C_;
    float* ao = aoB + (size_t)z * B_ * N_ * C_;
    const int tid = threadIdx.x;
    const int tx = tid & 15, ty = tid >> 4;
    const int bh = blockIdx.y;
    const int b = bh >> 3, h = bh & 7;
    const int r0 = blockIdx.x * QROWS;
    const float scale = 0.17677669529663687f;  // 32^-0.5

    // load q tile (128 x 32), pre-scaled, transposed
    const float* qg = q + ((size_t)b * N_ + r0) * C_ + h * D_;
    for (int e = tid; e < QROWS * 8; e += 256) {
        int i = e >> 3, dq = (e & 7) << 2;
        float4 v = *(const float4*)&qg[(size_t)i * C_ + dq];
        qsT[dq + 0][i] = v.x * scale; qsT[dq + 1][i] = v.y * scale;
        qsT[dq + 2][i] = v.z * scale; qsT[dq + 3][i] = v.w * scale;
    }

    float m[8], l[8];
    u64 O2[4][2] = {};
#pragma unroll
    for (int r = 0; r < 8; r++) { m[r] = -1e30f; l[r] = 0.f; }
    const float* kg = kv + (size_t)b * M_ * (2 * C_) + h * D_;

    for (int j0 = 0; j0 < M_; j0 += 64) {
        __syncthreads();   // prior PV done before overwriting ks/vs/Ps
        for (int e = tid; e < 64 * 8; e += 256) {
            int j = e >> 3, dq = (e & 7) << 2;
            const float* kr = kg + (size_t)(j0 + j) * (2 * C_);
            float4 kk = *(const float4*)&kr[dq];
            ksT[dq + 0][j] = kk.x; ksT[dq + 1][j] = kk.y;
            ksT[dq + 2][j] = kk.z; ksT[dq + 3][j] = kk.w;
            *(float4*)&vs[j][dq] = *(const float4*)&kr[C_ + dq];
        }
        __syncthreads();

        // S = q k^T : 4 row-pairs x 4 cols
        u64 S2[4][4] = {};
#pragma unroll
        for (int d = 0; d < 32; d++) {
            ulonglong2 qa = *(const ulonglong2*)&qsT[d][ty * 8];
            ulonglong2 qb = *(const ulonglong2*)&qsT[d][ty * 8 + 4];
            float4 kkv = *(const float4*)&ksT[d][tx * 4];
            u64 qp[4] = {qa.x, qa.y, qb.x, qb.y};
            u64 kp[4] = {pk2(kkv.x, kkv.x), pk2(kkv.y, kkv.y),
                         pk2(kkv.z, kkv.z), pk2(kkv.w, kkv.w)};
#pragma unroll
            for (int r = 0; r < 4; r++)
#pragma unroll
                for (int c = 0; c < 4; c++) fma2(S2[r][c], qp[r], kp[c]);
        }

        // online softmax (row stats across the 16 tx lanes)
        float corr[8];
#pragma unroll
        for (int r = 0; r < 8; r++) {
            float Sv[4];
#pragma unroll
            for (int c = 0; c < 4; c++) {
                float2 t = up2(S2[r >> 1][c]);
                Sv[c] = (r & 1) ? t.y : t.x;
            }
            float cm = fmaxf(fmaxf(Sv[0], Sv[1]), fmaxf(Sv[2], Sv[3]));
            cm = fmaxf(cm, __shfl_xor_sync(~0u, cm, 1));
            cm = fmaxf(cm, __shfl_xor_sync(~0u, cm, 2));
            cm = fmaxf(cm, __shfl_xor_sync(~0u, cm, 4));
            cm = fmaxf(cm, __shfl_xor_sync(~0u, cm, 8));
            float nm = fmaxf(m[r], cm);
            corr[r] = __expf(m[r] - nm);
            m[r] = nm;
            float ps = 0.f;
#pragma unroll
            for (int c = 0; c < 4; c++) {
                float p = __expf(Sv[c] - nm);
                Ps[tx * 4 + c][ty * 8 + r] = p;
                ps += p;
            }
            ps += __shfl_xor_sync(~0u, ps, 1);
            ps += __shfl_xor_sync(~0u, ps, 2);
            ps += __shfl_xor_sync(~0u, ps, 4);
            ps += __shfl_xor_sync(~0u, ps, 8);
            l[r] = l[r] * corr[r] + ps;
        }
#pragma unroll
        for (int p = 0; p < 4; p++) {
            u64 cp = pk2(corr[2 * p], corr[2 * p + 1]);
            mul2(O2[p][0], cp);
            mul2(O2[p][1], cp);
        }
        __syncthreads();   // Ps fully written before PV reads across lanes

        // O += P V : 4 row-pairs x 2 d-cols
#pragma unroll 8
        for (int j = 0; j < 64; j++) {
            ulonglong2 pA = *(const ulonglong2*)&Ps[j][ty * 8];
            ulonglong2 pB = *(const ulonglong2*)&Ps[j][ty * 8 + 4];
            float2 vv = *(const float2*)&vs[j][tx * 2];
            u64 vx = pk2(vv.x, vv.x), vy = pk2(vv.y, vv.y);
            u64 pp[4] = {pA.x, pA.y, pB.x, pB.y};
#pragma unroll
            for (int p = 0; p < 4; p++) {
                fma2(O2[p][0], pp[p], vx);
                fma2(O2[p][1], pp[p], vy);
            }
        }
    }
    float* og = ao + ((size_t)b * N_ + r0) * C_ + h * D_;
#pragma unroll
    for (int p = 0; p < 4; p++) {
        float2 o0 = up2(O2[p][0]), o1 = up2(O2[p][1]);
        int row = ty * 8 + 2 * p;
        float ia = 1.f / l[2 * p], ib = 1.f / l[2 * p + 1];
        *(float2*)&og[(size_t)row * C_ + tx * 2] =
            make_float2(o0.x * ia, o1.x * ia);
        *(float2*)&og[(size_t)(row + 1) * C_ + tx * 2] =
            make_float2(o0.y * ib, o1.y * ib);
    }
}

#define SMEM_ATT ((32 * 132 + 32 * 68 + 64 * 36 + 64 * 132) * 4)

// ---------------- launch ----------------
extern "C" void kernel_launch(void* const* d_in, const int* in_sizes, int n_in,
                              void* d_out, int out_size) {
    const float* x0     = (const float*)d_in[0];
    const float* x1     = (const float*)d_in[1];
    const float* Wq     = (const float*)d_in[2];
    const float* Wkv    = (const float*)d_in[3];
    const float* Wproj  = (const float*)d_in[4];
    const float* bproj  = (const float*)d_in[5];
    const float* Wsr    = (const float*)d_in[6];
    const float* bsr    = (const float*)d_in[7];
    const float* lnw0   = (const float*)d_in[8];
    const float* lnb0   = (const float*)d_in[9];
    const float* lnw1   = (const float*)d_in[10];
    const float* lnb1   = (const float*)d_in[11];
    float* out = (float*)d_out;

    float *q, *p, *xs, *kvb, *ao;
    cudaGetSymbolAddress((void**)&q,   g_q);
    cudaGetSymbolAddress((void**)&p,   g_p);
    cudaGetSymbolAddress((void**)&xs,  g_xs);
    cudaGetSymbolAddress((void**)&kvb, g_kv);
    cudaGetSymbolAddress((void**)&ao,  g_ao);

    cudaFuncSetAttribute(attention_k,
                         cudaFuncAttributeMaxDynamicSharedMemorySize, SMEM_ATT);

    const size_t sQ  = (size_t)B_ * N_ * C_;
    const size_t sP  = (size_t)B_ * M_ * 4 * C_;
    const size_t sXS = (size_t)B_ * M_ * C_;
    const size_t sKV = (size_t)B_ * M_ * 2 * C_;

    gemm128<<<dim3(C_ / 64, (B_ * N_) / 128, 2), 256>>>(
        q, q + sQ, x0, x1, Wq, nullptr, C_, C_);
    im2col_k<<<dim3((B_ * M_ * C_ + 255) / 256, 2), 256>>>(p, x0, x1);
    gemm128<<<dim3(C_ / 64, (B_ * M_) / 128, 2), 256>>>(
        xs, xs + sXS, p, p + sP, Wsr, bsr, C_, 4 * C_);
    layernorm_k<<<dim3(B_ * M_, 2), 256>>>(xs, lnw0, lnb0, lnw1, lnb1);
    gemm128<<<dim3((2 * C_) / 64, (B_ * M_) / 128, 2), 256>>>(
        kvb, kvb + sKV, xs, xs + sXS, Wkv, nullptr, 2 * C_, C_);
    attention_k<<<dim3(N_ / QROWS, B_ * H_, 2), 256, SMEM_ATT>>>(ao, q, kvb);
    gemm128<<<dim3(C_ / 64, (B_ * N_) / 128, 2), 256>>>(
        out, out + sQ, ao, ao + sQ, Wproj, bproj, C_, C_);
}

// round 5
// speedup vs baseline: 3.1640x; 1.1725x over previous
#include <cuda_runtime.h>
#include <cuda_bf16.h>
#include <math.h>
#include <cstdint>

// Problem constants
#define B_    2
#define N_    4096
#define C_    256
#define H_    8        // heads
#define D_    32       // head dim
#define M_    1024     // reduced tokens (32x32)
#define HW_   64       // spatial H=W

typedef unsigned long long u64;

// ---------------- packed f32x2 helpers (FFMA2, attention path) ----------------
__device__ __forceinline__ u64 pk2(float lo, float hi) {
    u64 r; asm("mov.b64 %0, {%1, %2};" : "=l"(r) : "f"(lo), "f"(hi)); return r;
}
__device__ __forceinline__ float2 up2(u64 p) {
    float2 f; asm("mov.b64 {%0, %1}, %2;" : "=f"(f.x), "=f"(f.y) : "l"(p)); return f;
}
__device__ __forceinline__ void fma2(u64& d, u64 a, u64 b) {
    asm("fma.rn.f32x2 %0, %1, %2, %0;" : "+l"(d) : "l"(a), "l"(b));
}
__device__ __forceinline__ void mul2(u64& d, u64 a) {
    asm("mul.rn.f32x2 %0, %0, %1;" : "+l"(d) : "l"(a));
}

// ---------------- warp-level bf16 MMA (m16n8k16) ----------------
__device__ __forceinline__ void mma16816(float* d, const uint32_t* a,
                                         const uint32_t* b) {
    asm volatile(
        "mma.sync.aligned.m16n8k16.row.col.f32.bf16.bf16.f32 "
        "{%0,%1,%2,%3}, {%4,%5,%6,%7}, {%8,%9}, {%0,%1,%2,%3};"
        : "+f"(d[0]), "+f"(d[1]), "+f"(d[2]), "+f"(d[3])
        : "r"(a[0]), "r"(a[1]), "r"(a[2]), "r"(a[3]), "r"(b[0]), "r"(b[1]));
}

// ---------------- scratch (device globals; both streams) ----------------
__device__ float g_q [2*B_*N_*C_];        // 16 MB : q projection
__device__ float g_p [2*B_*M_*C_*4];      // 16 MB : im2col patches
__device__ float g_xs[2*B_*M_*C_];        //  4 MB : reduced + LN tokens
__device__ float g_kv[2*B_*M_*2*C_];      //  8 MB : kv projection
__device__ float g_ao[2*B_*N_*C_];        // 16 MB : attention output

// ================= HMMA GEMM: out = A @ W^T (+bias) =================
// A: (Mr x K) f32 row-major, W: (Nc x K) f32 row-major, out f32 row-major.
// CTA tile 128x64, BK=64. Split-bf16 3 terms. 8 warps = 4(M) x 2(N),
// each warp 32x32 via 2x4 m16n8k16 frags. smem rows padded to 72 bf16.
#define GSTR 72                              // bf16 elements per smem row
#define GOFF_AHI 0
#define GOFF_ALO (128 * GSTR)                // 9216 elems
#define GOFF_BHI (2 * 128 * GSTR)            // 18432
#define GOFF_BLO (2 * 128 * GSTR + 64 * GSTR)
#define GSMEM_ELEMS (2 * 128 * GSTR + 2 * 64 * GSTR)   // 27648
#define GSMEM_BYTES (GSMEM_ELEMS * 2)                  // 55296

__device__ __forceinline__ void cvstore(__nv_bfloat16* hi, __nv_bfloat16* lo,
                                        int row, int k, float4 v) {
    __nv_bfloat16 h0 = __float2bfloat16_rn(v.x), h1 = __float2bfloat16_rn(v.y);
    __nv_bfloat16 h2 = __float2bfloat16_rn(v.z), h3 = __float2bfloat16_rn(v.w);
    __nv_bfloat162 H01; H01.x = h0; H01.y = h1;
    __nv_bfloat162 H23; H23.x = h2; H23.y = h3;
    __nv_bfloat162 L01, L23;
    L01.x = __float2bfloat16_rn(v.x - __bfloat162float(h0));
    L01.y = __float2bfloat16_rn(v.y - __bfloat162float(h1));
    L23.x = __float2bfloat16_rn(v.z - __bfloat162float(h2));
    L23.y = __float2bfloat16_rn(v.w - __bfloat162float(h3));
    int e = row * GSTR + k;
    *(__nv_bfloat162*)&hi[e]     = H01;
    *(__nv_bfloat162*)&hi[e + 2] = H23;
    *(__nv_bfloat162*)&lo[e]     = L01;
    *(__nv_bfloat162*)&lo[e + 2] = L23;
}

__global__ __launch_bounds__(256)
void gemm_tc(float* __restrict__ out0, float* __restrict__ out1,
             const float* __restrict__ A0, const float* __restrict__ A1,
             const float* __restrict__ W, const float* __restrict__ bias,
             int Nc, int K) {
    extern __shared__ __nv_bfloat16 sm[];
    __nv_bfloat16* sAh = sm + GOFF_AHI;
    __nv_bfloat16* sAl = sm + GOFF_ALO;
    __nv_bfloat16* sBh = sm + GOFF_BHI;
    __nv_bfloat16* sBl = sm + GOFF_BLO;

    const int z = blockIdx.z;
    const float* A = z ? A1 : A0;
    float* out = z ? out1 : out0;
    const int tid = threadIdx.x, wid = tid >> 5, lane = tid & 31;
    const int wm = wid & 3, wn = wid >> 2;        // warp 32-row / 32-col block
    const int fr = lane >> 2, fc = lane & 3;       // fragment row / col-pair
    const int i0 = blockIdx.y * 128, j0 = blockIdx.x * 64;

    float acc[2][4][4] = {};                       // [m-tile][n-tile][frag]

    for (int k0 = 0; k0 < K; k0 += 64) {
        // ---- fill smem: A 128x64, B 64x64, converted to hi/lo bf16 ----
#pragma unroll
        for (int r = 0; r < 8; r++) {
            int f = tid + 256 * r;
            int row = f >> 4, kq = (f & 15) << 2;
            float4 v = *(const float4*)&A[(size_t)(i0 + row) * K + k0 + kq];
            cvstore(sAh, sAl, row, kq, v);
        }
#pragma unroll
        for (int r = 0; r < 4; r++) {
            int f = tid + 256 * r;
            int row = f >> 4, kq = (f & 15) << 2;
            float4 v = *(const float4*)&W[(size_t)(j0 + row) * K + k0 + kq];
            cvstore(sBh, sBl, row, kq, v);
        }
        __syncthreads();

        // ---- 4 k16 steps ----
#pragma unroll
        for (int ks = 0; ks < 4; ks++) {
            const int kb = ks * 16 + fc * 2;
            uint32_t Ah[2][4], Al[2][4], Bh[4][2], Bl[4][2];
#pragma unroll
            for (int mt = 0; mt < 2; mt++) {
                int rbase = (wm * 32 + mt * 16 + fr) * GSTR + kb;
                Ah[mt][0] = *(const uint32_t*)&sAh[rbase];
                Ah[mt][1] = *(const uint32_t*)&sAh[rbase + 8 * GSTR];
                Ah[mt][2] = *(const uint32_t*)&sAh[rbase + 8];
                Ah[mt][3] = *(const uint32_t*)&sAh[rbase + 8 * GSTR + 8];
                Al[mt][0] = *(const uint32_t*)&sAl[rbase];
                Al[mt][1] = *(const uint32_t*)&sAl[rbase + 8 * GSTR];
                Al[mt][2] = *(const uint32_t*)&sAl[rbase + 8];
                Al[mt][3] = *(const uint32_t*)&sAl[rbase + 8 * GSTR + 8];
            }
#pragma unroll
            for (int nt = 0; nt < 4; nt++) {
                int rbase = (wn * 32 + nt * 8 + fr) * GSTR + kb;
                Bh[nt][0] = *(const uint32_t*)&sBh[rbase];
                Bh[nt][1] = *(const uint32_t*)&sBh[rbase + 8];
                Bl[nt][0] = *(const uint32_t*)&sBl[rbase];
                Bl[nt][1] = *(const uint32_t*)&sBl[rbase + 8];
            }
#pragma unroll
            for (int mt = 0; mt < 2; mt++)
#pragma unroll
                for (int nt = 0; nt < 4; nt++) {
                    mma16816(acc[mt][nt], Ah[mt], Bh[nt]);
                    mma16816(acc[mt][nt], Ah[mt], Bl[nt]);
                    mma16816(acc[mt][nt], Al[mt], Bh[nt]);
                }
        }
        __syncthreads();
    }

    // ---- epilogue: fragment -> gmem (float2 per half-row) ----
#pragma unroll
    for (int mt = 0; mt < 2; mt++) {
#pragma unroll
        for (int nt = 0; nt < 4; nt++) {
            int col = j0 + wn * 32 + nt * 8 + fc * 2;
            float bx = 0.f, by = 0.f;
            if (bias) { bx = bias[col]; by = bias[col + 1]; }
            int row0 = i0 + wm * 32 + mt * 16 + fr;
            *(float2*)&out[(size_t)row0 * Nc + col] =
                make_float2(acc[mt][nt][0] + bx, acc[mt][nt][1] + by);
            *(float2*)&out[(size_t)(row0 + 8) * Nc + col] =
                make_float2(acc[mt][nt][2] + bx, acc[mt][nt][3] + by);
        }
    }
}

// ---------------- im2col for 2x2 stride-2 conv ----------------
__global__ __launch_bounds__(256)
void im2col_k(float* __restrict__ Pb, const float* __restrict__ x0,
              const float* __restrict__ x1) {
    int idx = blockIdx.x * blockDim.x + threadIdx.x;
    if (idx >= B_ * M_ * C_) return;
    int z = blockIdx.y;
    const float* x = z ? x1 : x0;
    float* P = Pb + (size_t)z * B_ * M_ * 4 * C_;
    int cin = idx & (C_ - 1);
    int row = idx >> 8;
    int b   = row >> 10;
    int m   = row & (M_ - 1);
    int i = m >> 5, j = m & 31;
    const float* xb = x + (size_t)b * N_ * C_;
    float* pr = P + (size_t)row * (4 * C_) + cin * 4;
#pragma unroll
    for (int kh = 0; kh < 2; kh++)
#pragma unroll
        for (int kw = 0; kw < 2; kw++) {
            int n = (2 * i + kh) * HW_ + (2 * j + kw);
            pr[kh * 2 + kw] = xb[(size_t)n * C_ + cin];
        }
}

// ---------------- LayerNorm over C=256 ----------------
__global__ __launch_bounds__(256)
void layernorm_k(float* __restrict__ xsb,
                 const float* __restrict__ w0, const float* __restrict__ b0,
                 const float* __restrict__ w1, const float* __restrict__ b1) {
    int z = blockIdx.y;
    float* xs = xsb + (size_t)z * B_ * M_ * C_;
    const float* w = z ? w1 : w0;
    const float* bv = z ? b1 : b0;
    int row = blockIdx.x;
    int tid = threadIdx.x;
    float v = xs[(size_t)row * C_ + tid];
    float s = v, s2 = v * v;
#pragma unroll
    for (int o = 16; o > 0; o >>= 1) {
        s  += __shfl_xor_sync(~0u, s,  o);
        s2 += __shfl_xor_sync(~0u, s2, o);
    }
    __shared__ float rs[8], rs2[8];
    int wid = tid >> 5, lane = tid & 31;
    if (lane == 0) { rs[wid] = s; rs2[wid] = s2; }
    __syncthreads();
    float tot = 0.f, tot2 = 0.f;
#pragma unroll
    for (int i = 0; i < 8; i++) { tot += rs[i]; tot2 += rs2[i]; }
    float mu  = tot * (1.f / C_);
    float var = tot2 * (1.f / C_) - mu * mu;
    float inv = rsqrtf(var + 1e-5f);
    xs[(size_t)row * C_ + tid] = (v - mu) * inv * w[tid] + bv[tid];
}

// ---------------- fused flash-style attention (f32x2) ----------------
#define QROWS 128
__global__ __launch_bounds__(256)
void attention_k(float* __restrict__ aoB, const float* __restrict__ qB,
                 const float* __restrict__ kvB) {
    extern __shared__ float smf[];
    float (*qsT)[132] = (float(*)[132])smf;                              // [d][i]
    float (*ksT)[68]  = (float(*)[68])(smf + 32 * 132);                  // [d][j]
    float (*vs)[36]   = (float(*)[36])(smf + 32 * 132 + 32 * 68);        // [j][d]
    float (*Ps)[132]  = (float(*)[132])(smf + 32 * 132 + 32 * 68 + 64 * 36);

    const int z = blockIdx.z;
    const float* q  = qB  + (size_t)z * B_ * N_ * C_;
    const float* kv = kvB + (size_t)z * B_ * M_ * 2 * C_;
    float* ao = aoB + (size_t)z * B_ * N_ * C_;
    const int tid = threadIdx.x;
    const int tx = tid & 15, ty = tid >> 4;
    const int bh = blockIdx.y;
    const int b = bh >> 3, h = bh & 7;
    const int r0 = blockIdx.x * QROWS;
    const float scale = 0.17677669529663687f;  // 32^-0.5

    const float* qg = q + ((size_t)b * N_ + r0) * C_ + h * D_;
    for (int e = tid; e < QROWS * 8; e += 256) {
        int i = e >> 3, dq = (e & 7) << 2;
        float4 v = *(const float4*)&qg[(size_t)i * C_ + dq];
        qsT[dq + 0][i] = v.x * scale; qsT[dq + 1][i] = v.y * scale;
        qsT[dq + 2][i] = v.z * scale; qsT[dq + 3][i] = v.w * scale;
    }

    float m[8], l[8];
    u64 O2[4][2] = {};
#pragma unroll
    for (int r = 0; r < 8; r++) { m[r] = -1e30f; l[r] = 0.f; }
    const float* kg = kv + (size_t)b * M_ * (2 * C_) + h * D_;

    for (int j0 = 0; j0 < M_; j0 += 64) {
        __syncthreads();
        for (int e = tid; e < 64 * 8; e += 256) {
            int j = e >> 3, dq = (e & 7) << 2;
            const float* kr = kg + (size_t)(j0 + j) * (2 * C_);
            float4 kk = *(const float4*)&kr[dq];
            ksT[dq + 0][j] = kk.x; ksT[dq + 1][j] = kk.y;
            ksT[dq + 2][j] = kk.z; ksT[dq + 3][j] = kk.w;
            *(float4*)&vs[j][dq] = *(const float4*)&kr[C_ + dq];
        }
        __syncthreads();

        u64 S2[4][4] = {};
#pragma unroll
        for (int d = 0; d < 32; d++) {
            ulonglong2 qa = *(const ulonglong2*)&qsT[d][ty * 8];
            ulonglong2 qb = *(const ulonglong2*)&qsT[d][ty * 8 + 4];
            float4 kkv = *(const float4*)&ksT[d][tx * 4];
            u64 qp[4] = {qa.x, qa.y, qb.x, qb.y};
            u64 kp[4] = {pk2(kkv.x, kkv.x), pk2(kkv.y, kkv.y),
                         pk2(kkv.z, kkv.z), pk2(kkv.w, kkv.w)};
#pragma unroll
            for (int r = 0; r < 4; r++)
#pragma unroll
                for (int c = 0; c < 4; c++) fma2(S2[r][c], qp[r], kp[c]);
        }

        float corr[8];
#pragma unroll
        for (int r = 0; r < 8; r++) {
            float Sv[4];
#pragma unroll
            for (int c = 0; c < 4; c++) {
                float2 t = up2(S2[r >> 1][c]);
                Sv[c] = (r & 1) ? t.y : t.x;
            }
            float cm = fmaxf(fmaxf(Sv[0], Sv[1]), fmaxf(Sv[2], Sv[3]));
            cm = fmaxf(cm, __shfl_xor_sync(~0u, cm, 1));
            cm = fmaxf(cm, __shfl_xor_sync(~0u, cm, 2));
            cm = fmaxf(cm, __shfl_xor_sync(~0u, cm, 4));
            cm = fmaxf(cm, __shfl_xor_sync(~0u, cm, 8));
            float nm = fmaxf(m[r], cm);
            corr[r] = __expf(m[r] - nm);
            m[r] = nm;
            float ps = 0.f;
#pragma unroll
            for (int c = 0; c < 4; c++) {
                float p = __expf(Sv[c] - nm);
                Ps[tx * 4 + c][ty * 8 + r] = p;
                ps += p;
            }
            ps += __shfl_xor_sync(~0u, ps, 1);
            ps += __shfl_xor_sync(~0u, ps, 2);
            ps += __shfl_xor_sync(~0u, ps, 4);
            ps += __shfl_xor_sync(~0u, ps, 8);
            l[r] = l[r] * corr[r] + ps;
        }
#pragma unroll
        for (int p = 0; p < 4; p++) {
            u64 cp = pk2(corr[2 * p], corr[2 * p + 1]);
            mul2(O2[p][0], cp);
            mul2(O2[p][1], cp);
        }
        __syncthreads();

#pragma unroll 8
        for (int j = 0; j < 64; j++) {
            ulonglong2 pA = *(const ulonglong2*)&Ps[j][ty * 8];
            ulonglong2 pB = *(const ulonglong2*)&Ps[j][ty * 8 + 4];
            float2 vv = *(const float2*)&vs[j][tx * 2];
            u64 vx = pk2(vv.x, vv.x), vy = pk2(vv.y, vv.y);
            u64 pp[4] = {pA.x, pA.y, pB.x, pB.y};
#pragma unroll
            for (int p = 0; p < 4; p++) {
                fma2(O2[p][0], pp[p], vx);
                fma2(O2[p][1], pp[p], vy);
            }
        }
    }
    float* og = ao + ((size_t)b * N_ + r0) * C_ + h * D_;
#pragma unroll
    for (int p = 0; p < 4; p++) {
        float2 o0 = up2(O2[p][0]), o1 = up2(O2[p][1]);
        int row = ty * 8 + 2 * p;
        float ia = 1.f / l[2 * p], ib = 1.f / l[2 * p + 1];
        *(float2*)&og[(size_t)row * C_ + tx * 2] =
            make_float2(o0.x * ia, o1.x * ia);
        *(float2*)&og[(size_t)(row + 1) * C_ + tx * 2] =
            make_float2(o0.y * ib, o1.y * ib);
    }
}

#define SMEM_ATT ((32 * 132 + 32 * 68 + 64 * 36 + 64 * 132) * 4)

// ---------------- launch ----------------
extern "C" void kernel_launch(void* const* d_in, const int* in_sizes, int n_in,
                              void* d_out, int out_size) {
    const float* x0     = (const float*)d_in[0];
    const float* x1     = (const float*)d_in[1];
    const float* Wq     = (const float*)d_in[2];
    const float* Wkv    = (const float*)d_in[3];
    const float* Wproj  = (const float*)d_in[4];
    const float* bproj  = (const float*)d_in[5];
    const float* Wsr    = (const float*)d_in[6];
    const float* bsr    = (const float*)d_in[7];
    const float* lnw0   = (const float*)d_in[8];
    const float* lnb0   = (const float*)d_in[9];
    const float* lnw1   = (const float*)d_in[10];
    const float* lnb1   = (const float*)d_in[11];
    float* out = (float*)d_out;

    float *q, *p, *xs, *kvb, *ao;
    cudaGetSymbolAddress((void**)&q,   g_q);
    cudaGetSymbolAddress((void**)&p,   g_p);
    cudaGetSymbolAddress((void**)&xs,  g_xs);
    cudaGetSymbolAddress((void**)&kvb, g_kv);
    cudaGetSymbolAddress((void**)&ao,  g_ao);

    cudaFuncSetAttribute(attention_k,
                         cudaFuncAttributeMaxDynamicSharedMemorySize, SMEM_ATT);
    cudaFuncSetAttribute(gemm_tc,
                         cudaFuncAttributeMaxDynamicSharedMemorySize, GSMEM_BYTES);

    const size_t sQ  = (size_t)B_ * N_ * C_;
    const size_t sP  = (size_t)B_ * M_ * 4 * C_;
    const size_t sXS = (size_t)B_ * M_ * C_;
    const size_t sKV = (size_t)B_ * M_ * 2 * C_;

    // q = x @ Wq^T                (8192 x 256, K=256)
    gemm_tc<<<dim3(C_ / 64, (B_ * N_) / 128, 2), 256, GSMEM_BYTES>>>(
        q, q + sQ, x0, x1, Wq, nullptr, C_, C_);
    // im2col patches
    im2col_k<<<dim3((B_ * M_ * C_ + 255) / 256, 2), 256>>>(p, x0, x1);
    // xs = patches @ Wsr^T + bsr  (2048 x 256, K=1024)
    gemm_tc<<<dim3(C_ / 64, (B_ * M_) / 128, 2), 256, GSMEM_BYTES>>>(
        xs, xs + sXS, p, p + sP, Wsr, bsr, C_, 4 * C_);
    // layernorm (in place)
    layernorm_k<<<dim3(B_ * M_, 2), 256>>>(xs, lnw0, lnb0, lnw1, lnb1);
    // kv = xs @ Wkv^T             (2048 x 512, K=256)
    gemm_tc<<<dim3((2 * C_) / 64, (B_ * M_) / 128, 2), 256, GSMEM_BYTES>>>(
        kvb, kvb + sKV, xs, xs + sXS, Wkv, nullptr, 2 * C_, C_);
    // fused attention
    attention_k<<<dim3(N_ / QROWS, B_ * H_, 2), 256, SMEM_ATT>>>(ao, q, kvb);
    // y = ao @ Wproj^T + bproj
    gemm_tc<<<dim3(C_ / 64, (B_ * N_) / 128, 2), 256, GSMEM_BYTES>>>(
        out, out + sQ, ao, ao + sQ, Wproj, bproj, C_, C_);
}

// round 6
// speedup vs baseline: 6.2581x; 1.9779x over previous
#include <cuda_runtime.h>
#include <cuda_bf16.h>
#include <math.h>
#include <cstdint>

// Problem constants
#define B_    2
#define N_    4096
#define C_    256
#define H_    8        // heads
#define D_    32       // head dim
#define M_    1024     // reduced tokens (32x32)
#define HW_   64       // spatial H=W

typedef unsigned long long u64;

// ---------------- warp-level bf16 MMA (m16n8k16) ----------------
__device__ __forceinline__ void mma16816(float* d, const uint32_t* a,
                                         const uint32_t* b) {
    asm volatile(
        "mma.sync.aligned.m16n8k16.row.col.f32.bf16.bf16.f32 "
        "{%0,%1,%2,%3}, {%4,%5,%6,%7}, {%8,%9}, {%0,%1,%2,%3};"
        : "+f"(d[0]), "+f"(d[1]), "+f"(d[2]), "+f"(d[3])
        : "r"(a[0]), "r"(a[1]), "r"(a[2]), "r"(a[3]), "r"(b[0]), "r"(b[1]));
}

__device__ __forceinline__ uint32_t pkbf2(float x, float y) {
    __nv_bfloat162 t;
    t.x = __float2bfloat16_rn(x);
    t.y = __float2bfloat16_rn(y);
    return *(uint32_t*)&t;
}
// split pack: hi = bf16x2(x,y), lo = bf16x2(residuals)
__device__ __forceinline__ void pk_hl(float x, float y, uint32_t& hi, uint32_t& lo) {
    __nv_bfloat16 hx = __float2bfloat16_rn(x), hy = __float2bfloat16_rn(y);
    __nv_bfloat162 H; H.x = hx; H.y = hy;
    __nv_bfloat162 L;
    L.x = __float2bfloat16_rn(x - __bfloat162float(hx));
    L.y = __float2bfloat16_rn(y - __bfloat162float(hy));
    hi = *(uint32_t*)&H;
    lo = *(uint32_t*)&L;
}

// ---------------- scratch (device globals; both streams) ----------------
__device__ float g_q [2*B_*N_*C_];        // 16 MB : q projection
__device__ float g_p [2*B_*M_*C_*4];      // 16 MB : im2col patches
__device__ float g_xs[2*B_*M_*C_];        //  4 MB : reduced + LN tokens
__device__ float g_kv[2*B_*M_*2*C_];      //  8 MB : kv projection
__device__ float g_ao[2*B_*N_*C_];        // 16 MB : attention output

// ================= HMMA GEMM: out = A @ W^T (+bias) =================
#define GSTR 72
#define GOFF_AHI 0
#define GOFF_ALO (128 * GSTR)
#define GOFF_BHI (2 * 128 * GSTR)
#define GOFF_BLO (2 * 128 * GSTR + 64 * GSTR)
#define GSMEM_ELEMS (2 * 128 * GSTR + 2 * 64 * GSTR)
#define GSMEM_BYTES (GSMEM_ELEMS * 2)

__device__ __forceinline__ void cvstore(__nv_bfloat16* hi, __nv_bfloat16* lo,
                                        int row, int k, float4 v) {
    __nv_bfloat16 h0 = __float2bfloat16_rn(v.x), h1 = __float2bfloat16_rn(v.y);
    __nv_bfloat16 h2 = __float2bfloat16_rn(v.z), h3 = __float2bfloat16_rn(v.w);
    __nv_bfloat162 H01; H01.x = h0; H01.y = h1;
    __nv_bfloat162 H23; H23.x = h2; H23.y = h3;
    __nv_bfloat162 L01, L23;
    L01.x = __float2bfloat16_rn(v.x - __bfloat162float(h0));
    L01.y = __float2bfloat16_rn(v.y - __bfloat162float(h1));
    L23.x = __float2bfloat16_rn(v.z - __bfloat162float(h2));
    L23.y = __float2bfloat16_rn(v.w - __bfloat162float(h3));
    int e = row * GSTR + k;
    *(__nv_bfloat162*)&hi[e]     = H01;
    *(__nv_bfloat162*)&hi[e + 2] = H23;
    *(__nv_bfloat162*)&lo[e]     = L01;
    *(__nv_bfloat162*)&lo[e + 2] = L23;
}

__global__ __launch_bounds__(256)
void gemm_tc(float* __restrict__ out0, float* __restrict__ out1,
             const float* __restrict__ A0, const float* __restrict__ A1,
             const float* __restrict__ W, const float* __restrict__ bias,
             int Nc, int K) {
    extern __shared__ __nv_bfloat16 sm[];
    __nv_bfloat16* sAh = sm + GOFF_AHI;
    __nv_bfloat16* sAl = sm + GOFF_ALO;
    __nv_bfloat16* sBh = sm + GOFF_BHI;
    __nv_bfloat16* sBl = sm + GOFF_BLO;

    const int z = blockIdx.z;
    const float* A = z ? A1 : A0;
    float* out = z ? out1 : out0;
    const int tid = threadIdx.x, wid = tid >> 5, lane = tid & 31;
    const int wm = wid & 3, wn = wid >> 2;
    const int fr = lane >> 2, fc = lane & 3;
    const int i0 = blockIdx.y * 128, j0 = blockIdx.x * 64;

    float acc[2][4][4] = {};

    for (int k0 = 0; k0 < K; k0 += 64) {
#pragma unroll
        for (int r = 0; r < 8; r++) {
            int f = tid + 256 * r;
            int row = f >> 4, kq = (f & 15) << 2;
            float4 v = *(const float4*)&A[(size_t)(i0 + row) * K + k0 + kq];
            cvstore(sAh, sAl, row, kq, v);
        }
#pragma unroll
        for (int r = 0; r < 4; r++) {
            int f = tid + 256 * r;
            int row = f >> 4, kq = (f & 15) << 2;
            float4 v = *(const float4*)&W[(size_t)(j0 + row) * K + k0 + kq];
            cvstore(sBh, sBl, row, kq, v);
        }
        __syncthreads();

#pragma unroll
        for (int ks = 0; ks < 4; ks++) {
            const int kb = ks * 16 + fc * 2;
            uint32_t Ah[2][4], Al[2][4], Bh[4][2], Bl[4][2];
#pragma unroll
            for (int mt = 0; mt < 2; mt++) {
                int rbase = (wm * 32 + mt * 16 + fr) * GSTR + kb;
                Ah[mt][0] = *(const uint32_t*)&sAh[rbase];
                Ah[mt][1] = *(const uint32_t*)&sAh[rbase + 8 * GSTR];
                Ah[mt][2] = *(const uint32_t*)&sAh[rbase + 8];
                Ah[mt][3] = *(const uint32_t*)&sAh[rbase + 8 * GSTR + 8];
                Al[mt][0] = *(const uint32_t*)&sAl[rbase];
                Al[mt][1] = *(const uint32_t*)&sAl[rbase + 8 * GSTR];
                Al[mt][2] = *(const uint32_t*)&sAl[rbase + 8];
                Al[mt][3] = *(const uint32_t*)&sAl[rbase + 8 * GSTR + 8];
            }
#pragma unroll
            for (int nt = 0; nt < 4; nt++) {
                int rbase = (wn * 32 + nt * 8 + fr) * GSTR + kb;
                Bh[nt][0] = *(const uint32_t*)&sBh[rbase];
                Bh[nt][1] = *(const uint32_t*)&sBh[rbase + 8];
                Bl[nt][0] = *(const uint32_t*)&sBl[rbase];
                Bl[nt][1] = *(const uint32_t*)&sBl[rbase + 8];
            }
#pragma unroll
            for (int mt = 0; mt < 2; mt++)
#pragma unroll
                for (int nt = 0; nt < 4; nt++) {
                    mma16816(acc[mt][nt], Ah[mt], Bh[nt]);
                    mma16816(acc[mt][nt], Ah[mt], Bl[nt]);
                    mma16816(acc[mt][nt], Al[mt], Bh[nt]);
                }
        }
        __syncthreads();
    }

#pragma unroll
    for (int mt = 0; mt < 2; mt++) {
#pragma unroll
        for (int nt = 0; nt < 4; nt++) {
            int col = j0 + wn * 32 + nt * 8 + fc * 2;
            float bx = 0.f, by = 0.f;
            if (bias) { bx = bias[col]; by = bias[col + 1]; }
            int row0 = i0 + wm * 32 + mt * 16 + fr;
            *(float2*)&out[(size_t)row0 * Nc + col] =
                make_float2(acc[mt][nt][0] + bx, acc[mt][nt][1] + by);
            *(float2*)&out[(size_t)(row0 + 8) * Nc + col] =
                make_float2(acc[mt][nt][2] + bx, acc[mt][nt][3] + by);
        }
    }
}

// ---------------- im2col for 2x2 stride-2 conv ----------------
__global__ __launch_bounds__(256)
void im2col_k(float* __restrict__ Pb, const float* __restrict__ x0,
              const float* __restrict__ x1) {
    int idx = blockIdx.x * blockDim.x + threadIdx.x;
    if (idx >= B_ * M_ * C_) return;
    int z = blockIdx.y;
    const float* x = z ? x1 : x0;
    float* P = Pb + (size_t)z * B_ * M_ * 4 * C_;
    int cin = idx & (C_ - 1);
    int row = idx >> 8;
    int b   = row >> 10;
    int m   = row & (M_ - 1);
    int i = m >> 5, j = m & 31;
    const float* xb = x + (size_t)b * N_ * C_;
    float* pr = P + (size_t)row * (4 * C_) + cin * 4;
#pragma unroll
    for (int kh = 0; kh < 2; kh++)
#pragma unroll
        for (int kw = 0; kw < 2; kw++) {
            int n = (2 * i + kh) * HW_ + (2 * j + kw);
            pr[kh * 2 + kw] = xb[(size_t)n * C_ + cin];
        }
}

// ---------------- LayerNorm over C=256 ----------------
__global__ __launch_bounds__(256)
void layernorm_k(float* __restrict__ xsb,
                 const float* __restrict__ w0, const float* __restrict__ b0,
                 const float* __restrict__ w1, const float* __restrict__ b1) {
    int z = blockIdx.y;
    float* xs = xsb + (size_t)z * B_ * M_ * C_;
    const float* w = z ? w1 : w0;
    const float* bv = z ? b1 : b0;
    int row = blockIdx.x;
    int tid = threadIdx.x;
    float v = xs[(size_t)row * C_ + tid];
    float s = v, s2 = v * v;
#pragma unroll
    for (int o = 16; o > 0; o >>= 1) {
        s  += __shfl_xor_sync(~0u, s,  o);
        s2 += __shfl_xor_sync(~0u, s2, o);
    }
    __shared__ float rs[8], rs2[8];
    int wid = tid >> 5, lane = tid & 31;
    if (lane == 0) { rs[wid] = s; rs2[wid] = s2; }
    __syncthreads();
    float tot = 0.f, tot2 = 0.f;
#pragma unroll
    for (int i = 0; i < 8; i++) { tot += rs[i]; tot2 += rs2[i]; }
    float mu  = tot * (1.f / C_);
    float var = tot2 * (1.f / C_) - mu * mu;
    float inv = rsqrtf(var + 1e-5f);
    xs[(size_t)row * C_ + tid] = (v - mu) * inv * w[tid] + bv[tid];
}

// ================ HMMA fused flash attention ================
// grid (N/128, 16 bh, 2 streams), 256 threads = 8 warps x 16 q-rows.
// Per 64-key chunk: S = QK^T via m16n8k16 (3-term split-bf16), online
// softmax in accum fragments, P repacked in-register as A-fragments, PV MMA.
#define ASTR 40      // row stride for q/k (bf16)
#define VSTR 72      // row stride for vT (bf16)
__global__ __launch_bounds__(256)
void attention_k(float* __restrict__ aoB, const float* __restrict__ qB,
                 const float* __restrict__ kvB) {
    __shared__ __nv_bfloat16 qh[128][ASTR], ql[128][ASTR];
    __shared__ __nv_bfloat16 kh[64][ASTR],  kl[64][ASTR];
    __shared__ __nv_bfloat16 vhT[32][VSTR], vlT[32][VSTR];

    const int z = blockIdx.z;
    const float* q  = qB  + (size_t)z * B_ * N_ * C_;
    const float* kv = kvB + (size_t)z * B_ * M_ * 2 * C_;
    float* ao = aoB + (size_t)z * B_ * N_ * C_;
    const int tid = threadIdx.x, wid = tid >> 5, lane = tid & 31;
    const int fr = lane >> 2, fc = lane & 3;
    const int bh = blockIdx.y;
    const int b = bh >> 3, h = bh & 7;
    const int r0 = blockIdx.x * 128;
    const float scale = 0.17677669529663687f;  // 32^-0.5

    // ---- load Q (128 x 32), scale folded into hi/lo conversion ----
    const float* qg = q + ((size_t)b * N_ + r0) * C_ + h * D_;
#pragma unroll
    for (int r = 0; r < 4; r++) {
        int idx = tid + 256 * r;
        int row = idx >> 3, dq = (idx & 7) << 2;
        float4 v = *(const float4*)&qg[(size_t)row * C_ + dq];
        v.x *= scale; v.y *= scale; v.z *= scale; v.w *= scale;
        __nv_bfloat16 h0 = __float2bfloat16_rn(v.x), h1 = __float2bfloat16_rn(v.y);
        __nv_bfloat16 h2 = __float2bfloat16_rn(v.z), h3 = __float2bfloat16_rn(v.w);
        qh[row][dq + 0] = h0; qh[row][dq + 1] = h1;
        qh[row][dq + 2] = h2; qh[row][dq + 3] = h3;
        ql[row][dq + 0] = __float2bfloat16_rn(v.x - __bfloat162float(h0));
        ql[row][dq + 1] = __float2bfloat16_rn(v.y - __bfloat162float(h1));
        ql[row][dq + 2] = __float2bfloat16_rn(v.z - __bfloat162float(h2));
        ql[row][dq + 3] = __float2bfloat16_rn(v.w - __bfloat162float(h3));
    }

    float m0 = -1e30f, m1 = -1e30f, l0 = 0.f, l1 = 0.f;
    float O[4][4] = {};                 // [n-tile(d)][frag]
    const float* kg = kv + (size_t)b * M_ * (2 * C_) + h * D_;

    for (int j0 = 0; j0 < M_; j0 += 64) {
        __syncthreads();   // prior iteration's MMAs done before refill
        // ---- K chunk 64x32 -> kh/kl ----
#pragma unroll
        for (int r = 0; r < 2; r++) {
            int idx = tid + 256 * r;
            int j = idx >> 3, dq = (idx & 7) << 2;
            float4 v = *(const float4*)&kg[(size_t)(j0 + j) * (2 * C_) + dq];
            __nv_bfloat16 h0 = __float2bfloat16_rn(v.x), h1 = __float2bfloat16_rn(v.y);
            __nv_bfloat16 h2 = __float2bfloat16_rn(v.z), h3 = __float2bfloat16_rn(v.w);
            kh[j][dq + 0] = h0; kh[j][dq + 1] = h1;
            kh[j][dq + 2] = h2; kh[j][dq + 3] = h3;
            kl[j][dq + 0] = __float2bfloat16_rn(v.x - __bfloat162float(h0));
            kl[j][dq + 1] = __float2bfloat16_rn(v.y - __bfloat162float(h1));
            kl[j][dq + 2] = __float2bfloat16_rn(v.z - __bfloat162float(h2));
            kl[j][dq + 3] = __float2bfloat16_rn(v.w - __bfloat162float(h3));
        }
        // ---- V chunk 64x32 -> transposed vhT/vlT (j-pairs packed) ----
        {
            int jp = tid >> 3, dq = (tid & 7) << 2;   // jp 0..31
            const float* va = &kg[(size_t)(j0 + 2 * jp) * (2 * C_) + C_ + dq];
            float4 a = *(const float4*)va;
            float4 c = *(const float4*)(va + 2 * C_);
            float av[4] = {a.x, a.y, a.z, a.w};
            float cv[4] = {c.x, c.y, c.z, c.w};
#pragma unroll
            for (int i = 0; i < 4; i++) {
                __nv_bfloat16 ha = __float2bfloat16_rn(av[i]);
                __nv_bfloat16 hc = __float2bfloat16_rn(cv[i]);
                __nv_bfloat162 H; H.x = ha; H.y = hc;
                __nv_bfloat162 L;
                L.x = __float2bfloat16_rn(av[i] - __bfloat162float(ha));
                L.y = __float2bfloat16_rn(cv[i] - __bfloat162float(hc));
                *(__nv_bfloat162*)&vhT[dq + i][2 * jp] = H;
                *(__nv_bfloat162*)&vlT[dq + i][2 * jp] = L;
            }
        }
        __syncthreads();

        // ---- S = Q K^T : 8 n-tiles of 16x8, 2 k-steps, 3 terms ----
        float S[8][4] = {};
        const int arow = (wid << 4) + fr;
#pragma unroll
        for (int s = 0; s < 2; s++) {
            const int kb = (s << 4) + (fc << 1);
            uint32_t Ah[4], Al[4];
            Ah[0] = *(const uint32_t*)&qh[arow][kb];
            Ah[1] = *(const uint32_t*)&qh[arow + 8][kb];
            Ah[2] = *(const uint32_t*)&qh[arow][kb + 8];
            Ah[3] = *(const uint32_t*)&qh[arow + 8][kb + 8];
            Al[0] = *(const uint32_t*)&ql[arow][kb];
            Al[1] = *(const uint32_t*)&ql[arow + 8][kb];
            Al[2] = *(const uint32_t*)&ql[arow][kb + 8];
            Al[3] = *(const uint32_t*)&ql[arow + 8][kb + 8];
#pragma unroll
            for (int t = 0; t < 8; t++) {
                const int brow = (t << 3) + fr;
                uint32_t Bh[2], Bl[2];
                Bh[0] = *(const uint32_t*)&kh[brow][kb];
                Bh[1] = *(const uint32_t*)&kh[brow][kb + 8];
                Bl[0] = *(const uint32_t*)&kl[brow][kb];
                Bl[1] = *(const uint32_t*)&kl[brow][kb + 8];
                mma16816(S[t], Ah, Bh);
                mma16816(S[t], Ah, Bl);
                mma16816(S[t], Al, Bh);
            }
        }

        // ---- online softmax (rows fr and fr+8) ----
        float cm0 = -1e30f, cm1 = -1e30f;
#pragma unroll
        for (int t = 0; t < 8; t++) {
            cm0 = fmaxf(cm0, fmaxf(S[t][0], S[t][1]));
            cm1 = fmaxf(cm1, fmaxf(S[t][2], S[t][3]));
        }
        cm0 = fmaxf(cm0, __shfl_xor_sync(~0u, cm0, 1));
        cm0 = fmaxf(cm0, __shfl_xor_sync(~0u, cm0, 2));
        cm1 = fmaxf(cm1, __shfl_xor_sync(~0u, cm1, 1));
        cm1 = fmaxf(cm1, __shfl_xor_sync(~0u, cm1, 2));
        float nm0 = fmaxf(m0, cm0), nm1 = fmaxf(m1, cm1);
        float corr0 = __expf(m0 - nm0), corr1 = __expf(m1 - nm1);
        m0 = nm0; m1 = nm1;
        float ps0 = 0.f, ps1 = 0.f;
#pragma unroll
        for (int t = 0; t < 8; t++) {
            S[t][0] = __expf(S[t][0] - nm0);
            S[t][1] = __expf(S[t][1] - nm0);
            S[t][2] = __expf(S[t][2] - nm1);
            S[t][3] = __expf(S[t][3] - nm1);
            ps0 += S[t][0] + S[t][1];
            ps1 += S[t][2] + S[t][3];
        }
        ps0 += __shfl_xor_sync(~0u, ps0, 1);
        ps0 += __shfl_xor_sync(~0u, ps0, 2);
        ps1 += __shfl_xor_sync(~0u, ps1, 1);
        ps1 += __shfl_xor_sync(~0u, ps1, 2);
        l0 = l0 * corr0 + ps0;
        l1 = l1 * corr1 + ps1;
#pragma unroll
        for (int u = 0; u < 4; u++) {
            O[u][0] *= corr0; O[u][1] *= corr0;
            O[u][2] *= corr1; O[u][3] *= corr1;
        }

        // ---- pack P fragments (S frags t=2s,2s+1 become A frags for k-step s) ----
        uint32_t Ph[4][4], Pl[4][4];
#pragma unroll
        for (int s = 0; s < 4; s++) {
            pk_hl(S[2 * s][0],     S[2 * s][1],     Ph[s][0], Pl[s][0]);
            pk_hl(S[2 * s][2],     S[2 * s][3],     Ph[s][1], Pl[s][1]);
            pk_hl(S[2 * s + 1][0], S[2 * s + 1][1], Ph[s][2], Pl[s][2]);
            pk_hl(S[2 * s + 1][2], S[2 * s + 1][3], Ph[s][3], Pl[s][3]);
        }

        // ---- O += P V : 4 n-tiles(d) x 4 k-steps(j) x 3 terms ----
#pragma unroll
        for (int s = 0; s < 4; s++) {
            const int jb = (s << 4) + (fc << 1);
#pragma unroll
            for (int u = 0; u < 4; u++) {
                const int dn = (u << 3) + fr;
                uint32_t Bh[2], Bl[2];
                Bh[0] = *(const uint32_t*)&vhT[dn][jb];
                Bh[1] = *(const uint32_t*)&vhT[dn][jb + 8];
                Bl[0] = *(const uint32_t*)&vlT[dn][jb];
                Bl[1] = *(const uint32_t*)&vlT[dn][jb + 8];
                mma16816(O[u], Ph[s], Bh);
                mma16816(O[u], Ph[s], Bl);
                mma16816(O[u], Pl[s], Bh);
            }
        }
    }

    // ---- epilogue ----
    const float inv0 = 1.f / l0, inv1 = 1.f / l1;
    float* og = ao + ((size_t)b * N_ + r0) * C_ + h * D_;
    const int grow = (wid << 4) + fr;
#pragma unroll
    for (int u = 0; u < 4; u++) {
        int col = (u << 3) + (fc << 1);
        *(float2*)&og[(size_t)grow * C_ + col] =
            make_float2(O[u][0] * inv0, O[u][1] * inv0);
        *(float2*)&og[(size_t)(grow + 8) * C_ + col] =
            make_float2(O[u][2] * inv1, O[u][3] * inv1);
    }
}

// ---------------- launch ----------------
extern "C" void kernel_launch(void* const* d_in, const int* in_sizes, int n_in,
                              void* d_out, int out_size) {
    const float* x0     = (const float*)d_in[0];
    const float* x1     = (const float*)d_in[1];
    const float* Wq     = (const float*)d_in[2];
    const float* Wkv    = (const float*)d_in[3];
    const float* Wproj  = (const float*)d_in[4];
    const float* bproj  = (const float*)d_in[5];
    const float* Wsr    = (const float*)d_in[6];
    const float* bsr    = (const float*)d_in[7];
    const float* lnw0   = (const float*)d_in[8];
    const float* lnb0   = (const float*)d_in[9];
    const float* lnw1   = (const float*)d_in[10];
    const float* lnb1   = (const float*)d_in[11];
    float* out = (float*)d_out;

    float *q, *p, *xs, *kvb, *ao;
    cudaGetSymbolAddress((void**)&q,   g_q);
    cudaGetSymbolAddress((void**)&p,   g_p);
    cudaGetSymbolAddress((void**)&xs,  g_xs);
    cudaGetSymbolAddress((void**)&kvb, g_kv);
    cudaGetSymbolAddress((void**)&ao,  g_ao);

    cudaFuncSetAttribute(gemm_tc,
                         cudaFuncAttributeMaxDynamicSharedMemorySize, GSMEM_BYTES);

    const size_t sQ  = (size_t)B_ * N_ * C_;
    const size_t sP  = (size_t)B_ * M_ * 4 * C_;
    const size_t sXS = (size_t)B_ * M_ * C_;
    const size_t sKV = (size_t)B_ * M_ * 2 * C_;

    // q = x @ Wq^T                (8192 x 256, K=256)
    gemm_tc<<<dim3(C_ / 64, (B_ * N_) / 128, 2), 256, GSMEM_BYTES>>>(
        q, q + sQ, x0, x1, Wq, nullptr, C_, C_);
    // im2col patches
    im2col_k<<<dim3((B_ * M_ * C_ + 255) / 256, 2), 256>>>(p, x0, x1);
    // xs = patches @ Wsr^T + bsr  (2048 x 256, K=1024)
    gemm_tc<<<dim3(C_ / 64, (B_ * M_) / 128, 2), 256, GSMEM_BYTES>>>(
        xs, xs + sXS, p, p + sP, Wsr, bsr, C_, 4 * C_);
    // layernorm (in place)
    layernorm_k<<<dim3(B_ * M_, 2), 256>>>(xs, lnw0, lnb0, lnw1, lnb1);
    // kv = xs @ Wkv^T             (2048 x 512, K=256)
    gemm_tc<<<dim3((2 * C_) / 64, (B_ * M_) / 128, 2), 256, GSMEM_BYTES>>>(
        kvb, kvb + sKV, xs, xs + sXS, Wkv, nullptr, 2 * C_, C_);
    // fused attention (HMMA)
    attention_k<<<dim3(N_ / 128, B_ * H_, 2), 256>>>(ao, q, kvb);
    // y = ao @ Wproj^T + bproj
    gemm_tc<<<dim3(C_ / 64, (B_ * N_) / 128, 2), 256, GSMEM_BYTES>>>(
        out, out + sQ, ao, ao + sQ, Wproj, bproj, C_, C_);
}

// round 7
// speedup vs baseline: 6.2990x; 1.0065x over previous
#include <cuda_runtime.h>
#include <cuda_bf16.h>
#include <math.h>
#include <cstdint>

// Problem constants
#define B_    2
#define N_    4096
#define C_    256
#define H_    8        // heads
#define D_    32       // head dim
#define M_    1024     // reduced tokens (32x32)
#define HW_   64       // spatial H=W

typedef unsigned long long u64;

// ---------------- warp-level bf16 MMA (m16n8k16) ----------------
__device__ __forceinline__ void mma16816(float* d, const uint32_t* a,
                                         const uint32_t* b) {
    asm volatile(
        "mma.sync.aligned.m16n8k16.row.col.f32.bf16.bf16.f32 "
        "{%0,%1,%2,%3}, {%4,%5,%6,%7}, {%8,%9}, {%0,%1,%2,%3};"
        : "+f"(d[0]), "+f"(d[1]), "+f"(d[2]), "+f"(d[3])
        : "r"(a[0]), "r"(a[1]), "r"(a[2]), "r"(a[3]), "r"(b[0]), "r"(b[1]));
}

// split pack: hi = bf16x2(x,y), lo = bf16x2(residuals)
__device__ __forceinline__ void pk_hl(float x, float y, uint32_t& hi, uint32_t& lo) {
    __nv_bfloat16 hx = __float2bfloat16_rn(x), hy = __float2bfloat16_rn(y);
    __nv_bfloat162 H; H.x = hx; H.y = hy;
    __nv_bfloat162 L;
    L.x = __float2bfloat16_rn(x - __bfloat162float(hx));
    L.y = __float2bfloat16_rn(y - __bfloat162float(hy));
    hi = *(uint32_t*)&H;
    lo = *(uint32_t*)&L;
}
__device__ __forceinline__ void st_split(__nv_bfloat16* H, __nv_bfloat16* L,
                                         size_t off, float x, float y) {
    uint32_t h, l;
    pk_hl(x, y, h, l);
    *(uint32_t*)&H[off] = h;
    *(uint32_t*)&L[off] = l;
}

// ---------------- scratch (device globals; both streams) ----------------
__device__ __nv_bfloat16 g_xh [2*B_*N_*C_],   g_xl [2*B_*N_*C_];
__device__ __nv_bfloat16 g_qh [2*B_*N_*C_],   g_ql [2*B_*N_*C_];     // pre-scaled
__device__ __nv_bfloat16 g_ph [2*B_*M_*4*C_], g_pl [2*B_*M_*4*C_];
__device__ float         g_xsf[2*B_*M_*C_];
__device__ __nv_bfloat16 g_xsh[2*B_*M_*C_],   g_xsl[2*B_*M_*C_];
__device__ __nv_bfloat16 g_kvh[2*B_*M_*2*C_], g_kvl[2*B_*M_*2*C_];
__device__ __nv_bfloat16 g_aoh[2*B_*N_*C_],   g_aol[2*B_*N_*C_];
__device__ __nv_bfloat16 g_wqh [C_*C_],   g_wql [C_*C_];
__device__ __nv_bfloat16 g_wkvh[2*C_*C_], g_wkvl[2*C_*C_];
__device__ __nv_bfloat16 g_wprh[C_*C_],   g_wprl[C_*C_];
__device__ __nv_bfloat16 g_wsrh[4*C_*C_], g_wsrl[4*C_*C_];

// ---------------- generic f32 -> hi/lo bf16 split ----------------
__global__ __launch_bounds__(256)
void split_k(__nv_bfloat16* __restrict__ H, __nv_bfloat16* __restrict__ L,
             const float* __restrict__ S, int n, float scale) {
    int i = (blockIdx.x * 256 + threadIdx.x) * 4;
    if (i >= n) return;
    float4 v = *(const float4*)&S[i];
    v.x *= scale; v.y *= scale; v.z *= scale; v.w *= scale;
    uint32_t h0, l0, h1, l1;
    pk_hl(v.x, v.y, h0, l0);
    pk_hl(v.z, v.w, h1, l1);
    *(uint32_t*)&H[i]     = h0; *(uint32_t*)&H[i + 2] = h1;
    *(uint32_t*)&L[i]     = l0; *(uint32_t*)&L[i + 2] = l1;
}

// ================= HMMA GEMM on pre-split inputs =================
// out = A @ W^T; A,W given as hi/lo bf16 (row-major, K contig).
// out: f32 (+bias) if !splitout, else hi/lo bf16 scaled by oscale.
#define GSTR 72
__device__ __nv_bfloat16* gsm_ptr;  // (unused; dynamic smem below)
#define GSMEM_ELEMS (2 * 128 * GSTR + 2 * 64 * GSTR)
#define GSMEM_BYTES (GSMEM_ELEMS * 2)

__global__ __launch_bounds__(256)
void gemm_s(float* __restrict__ outf,
            __nv_bfloat16* __restrict__ outh, __nv_bfloat16* __restrict__ outl,
            const __nv_bfloat16* __restrict__ Ah, const __nv_bfloat16* __restrict__ Al,
            const __nv_bfloat16* __restrict__ Bh, const __nv_bfloat16* __restrict__ Bl,
            const float* __restrict__ bias, int Nc, int K,
            size_t strA, size_t strO, float oscale, int splitout) {
    extern __shared__ __nv_bfloat16 sm[];
    __nv_bfloat16* sAh = sm;
    __nv_bfloat16* sAl = sm + 128 * GSTR;
    __nv_bfloat16* sBh = sm + 2 * 128 * GSTR;
    __nv_bfloat16* sBl = sm + 2 * 128 * GSTR + 64 * GSTR;

    const int z = blockIdx.z;
    Ah += z * strA; Al += z * strA;
    const int tid = threadIdx.x, wid = tid >> 5, lane = tid & 31;
    const int wm = wid & 3, wn = wid >> 2;
    const int fr = lane >> 2, fc = lane & 3;
    const int i0 = blockIdx.y * 128, j0 = blockIdx.x * 64;

    float acc[2][4][4] = {};

    for (int k0 = 0; k0 < K; k0 += 64) {
        // A tiles: 128 x 64 bf16 per plane, uint4 copies
#pragma unroll
        for (int r = 0; r < 4; r++) {
            int f = tid + 256 * r;
            int row = f >> 3, kq = (f & 7) << 3;
            size_t ga = (size_t)(i0 + row) * K + k0 + kq;
            *(uint4*)&sAh[row * GSTR + kq] = *(const uint4*)&Ah[ga];
            *(uint4*)&sAl[row * GSTR + kq] = *(const uint4*)&Al[ga];
        }
        // B tiles: 64 x 64
#pragma unroll
        for (int r = 0; r < 2; r++) {
            int f = tid + 256 * r;
            int row = f >> 3, kq = (f & 7) << 3;
            size_t gb = (size_t)(j0 + row) * K + k0 + kq;
            *(uint4*)&sBh[row * GSTR + kq] = *(const uint4*)&Bh[gb];
            *(uint4*)&sBl[row * GSTR + kq] = *(const uint4*)&Bl[gb];
        }
        __syncthreads();

#pragma unroll
        for (int ks = 0; ks < 4; ks++) {
            const int kb = ks * 16 + fc * 2;
            uint32_t Ahf[2][4], Alf[2][4], Bhf[4][2], Blf[4][2];
#pragma unroll
            for (int mt = 0; mt < 2; mt++) {
                int rbase = (wm * 32 + mt * 16 + fr) * GSTR + kb;
                Ahf[mt][0] = *(const uint32_t*)&sAh[rbase];
                Ahf[mt][1] = *(const uint32_t*)&sAh[rbase + 8 * GSTR];
                Ahf[mt][2] = *(const uint32_t*)&sAh[rbase + 8];
                Ahf[mt][3] = *(const uint32_t*)&sAh[rbase + 8 * GSTR + 8];
                Alf[mt][0] = *(const uint32_t*)&sAl[rbase];
                Alf[mt][1] = *(const uint32_t*)&sAl[rbase + 8 * GSTR];
                Alf[mt][2] = *(const uint32_t*)&sAl[rbase + 8];
                Alf[mt][3] = *(const uint32_t*)&sAl[rbase + 8 * GSTR + 8];
            }
#pragma unroll
            for (int nt = 0; nt < 4; nt++) {
                int rbase = (wn * 32 + nt * 8 + fr) * GSTR + kb;
                Bhf[nt][0] = *(const uint32_t*)&sBh[rbase];
                Bhf[nt][1] = *(const uint32_t*)&sBh[rbase + 8];
                Blf[nt][0] = *(const uint32_t*)&sBl[rbase];
                Blf[nt][1] = *(const uint32_t*)&sBl[rbase + 8];
            }
#pragma unroll
            for (int mt = 0; mt < 2; mt++)
#pragma unroll
                for (int nt = 0; nt < 4; nt++) {
                    mma16816(acc[mt][nt], Ahf[mt], Bhf[nt]);
                    mma16816(acc[mt][nt], Ahf[mt], Blf[nt]);
                    mma16816(acc[mt][nt], Alf[mt], Bhf[nt]);
                }
        }
        __syncthreads();
    }

    if (!splitout) {
        float* out = outf + z * strO;
#pragma unroll
        for (int mt = 0; mt < 2; mt++)
#pragma unroll
            for (int nt = 0; nt < 4; nt++) {
                int col = j0 + wn * 32 + nt * 8 + fc * 2;
                float bx = 0.f, by = 0.f;
                if (bias) { bx = bias[col]; by = bias[col + 1]; }
                int row0 = i0 + wm * 32 + mt * 16 + fr;
                *(float2*)&out[(size_t)row0 * Nc + col] =
                    make_float2(acc[mt][nt][0] + bx, acc[mt][nt][1] + by);
                *(float2*)&out[(size_t)(row0 + 8) * Nc + col] =
                    make_float2(acc[mt][nt][2] + bx, acc[mt][nt][3] + by);
            }
    } else {
        __nv_bfloat16* oh = outh + z * strO;
        __nv_bfloat16* ol = outl + z * strO;
#pragma unroll
        for (int mt = 0; mt < 2; mt++)
#pragma unroll
            for (int nt = 0; nt < 4; nt++) {
                int col = j0 + wn * 32 + nt * 8 + fc * 2;
                int row0 = i0 + wm * 32 + mt * 16 + fr;
                st_split(oh, ol, (size_t)row0 * Nc + col,
                         acc[mt][nt][0] * oscale, acc[mt][nt][1] * oscale);
                st_split(oh, ol, (size_t)(row0 + 8) * Nc + col,
                         acc[mt][nt][2] * oscale, acc[mt][nt][3] * oscale);
            }
    }
}

// ---------------- im2col -> split bf16 patches ----------------
__global__ __launch_bounds__(256)
void im2col_k(__nv_bfloat16* __restrict__ Phb, __nv_bfloat16* __restrict__ Plb,
              const float* __restrict__ x0, const float* __restrict__ x1) {
    int idx = blockIdx.x * blockDim.x + threadIdx.x;
    if (idx >= B_ * M_ * C_) return;
    int z = blockIdx.y;
    const float* x = z ? x1 : x0;
    size_t zoff = (size_t)z * B_ * M_ * 4 * C_;
    int cin = idx & (C_ - 1);
    int row = idx >> 8;
    int b   = row >> 10;
    int m   = row & (M_ - 1);
    int i = m >> 5, j = m & 31;
    const float* xb = x + (size_t)b * N_ * C_;
    float v[4];
#pragma unroll
    for (int kh = 0; kh < 2; kh++)
#pragma unroll
        for (int kw = 0; kw < 2; kw++) {
            int n = (2 * i + kh) * HW_ + (2 * j + kw);
            v[kh * 2 + kw] = xb[(size_t)n * C_ + cin];
        }
    size_t base = zoff + (size_t)row * (4 * C_) + cin * 4;
    uint32_t h0, l0, h1, l1;
    pk_hl(v[0], v[1], h0, l0);
    pk_hl(v[2], v[3], h1, l1);
    *(uint32_t*)&Phb[base]     = h0; *(uint32_t*)&Phb[base + 2] = h1;
    *(uint32_t*)&Plb[base]     = l0; *(uint32_t*)&Plb[base + 2] = l1;
}

// ---------------- LayerNorm over C=256, split bf16 out ----------------
__global__ __launch_bounds__(256)
void layernorm_k(const float* __restrict__ xsf,
                 __nv_bfloat16* __restrict__ xsh, __nv_bfloat16* __restrict__ xsl,
                 const float* __restrict__ w0, const float* __restrict__ b0,
                 const float* __restrict__ w1, const float* __restrict__ b1) {
    int z = blockIdx.y;
    size_t zoff = (size_t)z * B_ * M_ * C_;
    const float* w = z ? w1 : w0;
    const float* bv = z ? b1 : b0;
    int row = blockIdx.x;
    int tid = threadIdx.x;
    float v = xsf[zoff + (size_t)row * C_ + tid];
    float s = v, s2 = v * v;
#pragma unroll
    for (int o = 16; o > 0; o >>= 1) {
        s  += __shfl_xor_sync(~0u, s,  o);
        s2 += __shfl_xor_sync(~0u, s2, o);
    }
    __shared__ float rs[8], rs2[8];
    int wid = tid >> 5, lane = tid & 31;
    if (lane == 0) { rs[wid] = s; rs2[wid] = s2; }
    __syncthreads();
    float tot = 0.f, tot2 = 0.f;
#pragma unroll
    for (int i = 0; i < 8; i++) { tot += rs[i]; tot2 += rs2[i]; }
    float mu  = tot * (1.f / C_);
    float var = tot2 * (1.f / C_) - mu * mu;
    float inv = rsqrtf(var + 1e-5f);
    float y = (v - mu) * inv * w[tid] + bv[tid];
    __nv_bfloat16 hb = __float2bfloat16_rn(y);
    size_t o = zoff + (size_t)row * C_ + tid;
    xsh[o] = hb;
    xsl[o] = __float2bfloat16_rn(y - __bfloat162float(hb));
}

// ================ HMMA fused flash attention (pre-split inputs) ================
// grid (N/128, 16 bh, 2 streams), 256 threads = 8 warps x 16 q-rows.
#define ASTR 40
#define VSTR 72
__global__ __launch_bounds__(256)
void attention_k(__nv_bfloat16* __restrict__ aohB, __nv_bfloat16* __restrict__ aolB,
                 const __nv_bfloat16* __restrict__ qhB, const __nv_bfloat16* __restrict__ qlB,
                 const __nv_bfloat16* __restrict__ kvhB, const __nv_bfloat16* __restrict__ kvlB) {
    __shared__ __nv_bfloat16 qh[128][ASTR], ql[128][ASTR];
    __shared__ __nv_bfloat16 kh[64][ASTR],  kl[64][ASTR];
    __shared__ __nv_bfloat16 vhT[32][VSTR], vlT[32][VSTR];

    const int z = blockIdx.z;
    const size_t sQ  = (size_t)B_ * N_ * C_;
    const size_t sKV = (size_t)B_ * M_ * 2 * C_;
    const __nv_bfloat16* qgh = qhB + z * sQ;
    const __nv_bfloat16* qgl = qlB + z * sQ;
    const __nv_bfloat16* kvh = kvhB + z * sKV;
    const __nv_bfloat16* kvl = kvlB + z * sKV;
    __nv_bfloat16* aoh = aohB + z * sQ;
    __nv_bfloat16* aol = aolB + z * sQ;
    const int tid = threadIdx.x, wid = tid >> 5, lane = tid & 31;
    const int fr = lane >> 2, fc = lane & 3;
    const int bh = blockIdx.y;
    const int b = bh >> 3, h = bh & 7;
    const int r0 = blockIdx.x * 128;

    // ---- Q tile copy (pre-scaled, pre-split) ----
    const size_t qbase = ((size_t)b * N_ + r0) * C_ + h * D_;
#pragma unroll
    for (int r = 0; r < 2; r++) {
        int idx = tid + 256 * r;
        int row = idx >> 2, kq = (idx & 3) << 3;
        *(uint4*)&qh[row][kq] = *(const uint4*)&qgh[qbase + (size_t)row * C_ + kq];
        *(uint4*)&ql[row][kq] = *(const uint4*)&qgl[qbase + (size_t)row * C_ + kq];
    }

    float m0 = -1e30f, m1 = -1e30f, l0 = 0.f, l1 = 0.f;
    float O[4][4] = {};
    const size_t kbase = (size_t)b * M_ * (2 * C_) + h * D_;

    for (int j0 = 0; j0 < M_; j0 += 64) {
        __syncthreads();
        // ---- K chunk copy 64x32 ----
        {
            int j = tid >> 2, kq = (tid & 3) << 3;
            size_t ga = kbase + (size_t)(j0 + j) * (2 * C_) + kq;
            *(uint4*)&kh[j][kq] = *(const uint4*)&kvh[ga];
            *(uint4*)&kl[j][kq] = *(const uint4*)&kvl[ga];
        }
        // ---- V chunk transpose 64x32 -> vT[32][64] (PRMT repack) ----
        {
            int jp = tid >> 3, dq = (tid & 7) << 2;   // jp 0..31, dq 0..28
            size_t ga = kbase + (size_t)(j0 + 2 * jp) * (2 * C_) + C_ + dq;
            uint2 ah = *(const uint2*)&kvh[ga];
            uint2 ch = *(const uint2*)&kvh[ga + 2 * C_];
            uint2 al = *(const uint2*)&kvl[ga];
            uint2 cl = *(const uint2*)&kvl[ga + 2 * C_];
            *(uint32_t*)&vhT[dq + 0][2 * jp] = __byte_perm(ah.x, ch.x, 0x5410);
            *(uint32_t*)&vhT[dq + 1][2 * jp] = __byte_perm(ah.x, ch.x, 0x7632);
            *(uint32_t*)&vhT[dq + 2][2 * jp] = __byte_perm(ah.y, ch.y, 0x5410);
            *(uint32_t*)&vhT[dq + 3][2 * jp] = __byte_perm(ah.y, ch.y, 0x7632);
            *(uint32_t*)&vlT[dq + 0][2 * jp] = __byte_perm(al.x, cl.x, 0x5410);
            *(uint32_t*)&vlT[dq + 1][2 * jp] = __byte_perm(al.x, cl.x, 0x7632);
            *(uint32_t*)&vlT[dq + 2][2 * jp] = __byte_perm(al.y, cl.y, 0x5410);
            *(uint32_t*)&vlT[dq + 3][2 * jp] = __byte_perm(al.y, cl.y, 0x7632);
        }
        __syncthreads();

        // ---- S = Q K^T ----
        float S[8][4] = {};
        const int arow = (wid << 4) + fr;
#pragma unroll
        for (int s = 0; s < 2; s++) {
            const int kb = (s << 4) + (fc << 1);
            uint32_t Ah[4], Al[4];
            Ah[0] = *(const uint32_t*)&qh[arow][kb];
            Ah[1] = *(const uint32_t*)&qh[arow + 8][kb];
            Ah[2] = *(const uint32_t*)&qh[arow][kb + 8];
            Ah[3] = *(const uint32_t*)&qh[arow + 8][kb + 8];
            Al[0] = *(const uint32_t*)&ql[arow][kb];
            Al[1] = *(const uint32_t*)&ql[arow + 8][kb];
            Al[2] = *(const uint32_t*)&ql[arow][kb + 8];
            Al[3] = *(const uint32_t*)&ql[arow + 8][kb + 8];
#pragma unroll
            for (int t = 0; t < 8; t++) {
                const int brow = (t << 3) + fr;
                uint32_t Bh[2], Bl[2];
                Bh[0] = *(const uint32_t*)&kh[brow][kb];
                Bh[1] = *(const uint32_t*)&kh[brow][kb + 8];
                Bl[0] = *(const uint32_t*)&kl[brow][kb];
                Bl[1] = *(const uint32_t*)&kl[brow][kb + 8];
                mma16816(S[t], Ah, Bh);
                mma16816(S[t], Ah, Bl);
                mma16816(S[t], Al, Bh);
            }
        }

        // ---- online softmax ----
        float cm0 = -1e30f, cm1 = -1e30f;
#pragma unroll
        for (int t = 0; t < 8; t++) {
            cm0 = fmaxf(cm0, fmaxf(S[t][0], S[t][1]));
            cm1 = fmaxf(cm1, fmaxf(S[t][2], S[t][3]));
        }
        cm0 = fmaxf(cm0, __shfl_xor_sync(~0u, cm0, 1));
        cm0 = fmaxf(cm0, __shfl_xor_sync(~0u, cm0, 2));
        cm1 = fmaxf(cm1, __shfl_xor_sync(~0u, cm1, 1));
        cm1 = fmaxf(cm1, __shfl_xor_sync(~0u, cm1, 2));
        float nm0 = fmaxf(m0, cm0), nm1 = fmaxf(m1, cm1);
        float corr0 = __expf(m0 - nm0), corr1 = __expf(m1 - nm1);
        m0 = nm0; m1 = nm1;
        float ps0 = 0.f, ps1 = 0.f;
#pragma unroll
        for (int t = 0; t < 8; t++) {
            S[t][0] = __expf(S[t][0] - nm0);
            S[t][1] = __expf(S[t][1] - nm0);
            S[t][2] = __expf(S[t][2] - nm1);
            S[t][3] = __expf(S[t][3] - nm1);
            ps0 += S[t][0] + S[t][1];
            ps1 += S[t][2] + S[t][3];
        }
        ps0 += __shfl_xor_sync(~0u, ps0, 1);
        ps0 += __shfl_xor_sync(~0u, ps0, 2);
        ps1 += __shfl_xor_sync(~0u, ps1, 1);
        ps1 += __shfl_xor_sync(~0u, ps1, 2);
        l0 = l0 * corr0 + ps0;
        l1 = l1 * corr1 + ps1;
#pragma unroll
        for (int u = 0; u < 4; u++) {
            O[u][0] *= corr0; O[u][1] *= corr0;
            O[u][2] *= corr1; O[u][3] *= corr1;
        }

        // ---- pack P as A-fragments ----
        uint32_t Ph[4][4], Pl[4][4];
#pragma unroll
        for (int s = 0; s < 4; s++) {
            pk_hl(S[2 * s][0],     S[2 * s][1],     Ph[s][0], Pl[s][0]);
            pk_hl(S[2 * s][2],     S[2 * s][3],     Ph[s][1], Pl[s][1]);
            pk_hl(S[2 * s + 1][0], S[2 * s + 1][1], Ph[s][2], Pl[s][2]);
            pk_hl(S[2 * s + 1][2], S[2 * s + 1][3], Ph[s][3], Pl[s][3]);
        }

        // ---- O += P V ----
#pragma unroll
        for (int s = 0; s < 4; s++) {
            const int jb = (s << 4) + (fc << 1);
#pragma unroll
            for (int u = 0; u < 4; u++) {
                const int dn = (u << 3) + fr;
                uint32_t Bh[2], Bl[2];
                Bh[0] = *(const uint32_t*)&vhT[dn][jb];
                Bh[1] = *(const uint32_t*)&vhT[dn][jb + 8];
                Bl[0] = *(const uint32_t*)&vlT[dn][jb];
                Bl[1] = *(const uint32_t*)&vlT[dn][jb + 8];
                mma16816(O[u], Ph[s], Bh);
                mma16816(O[u], Ph[s], Bl);
                mma16816(O[u], Pl[s], Bh);
            }
        }
    }

    // ---- epilogue: split bf16 out for the proj GEMM ----
    const float inv0 = 1.f / l0, inv1 = 1.f / l1;
    const size_t obase = ((size_t)b * N_ + r0) * C_ + h * D_;
    const int grow = (wid << 4) + fr;
#pragma unroll
    for (int u = 0; u < 4; u++) {
        int col = (u << 3) + (fc << 1);
        st_split(aoh, aol, obase + (size_t)grow * C_ + col,
                 O[u][0] * inv0, O[u][1] * inv0);
        st_split(aoh, aol, obase + (size_t)(grow + 8) * C_ + col,
                 O[u][2] * inv1, O[u][3] * inv1);
    }
}

// ---------------- launch ----------------
extern "C" void kernel_launch(void* const* d_in, const int* in_sizes, int n_in,
                              void* d_out, int out_size) {
    const float* x0     = (const float*)d_in[0];
    const float* x1     = (const float*)d_in[1];
    const float* Wq     = (const float*)d_in[2];
    const float* Wkv    = (const float*)d_in[3];
    const float* Wproj  = (const float*)d_in[4];
    const float* bproj  = (const float*)d_in[5];
    const float* Wsr    = (const float*)d_in[6];
    const float* bsr    = (const float*)d_in[7];
    const float* lnw0   = (const float*)d_in[8];
    const float* lnb0   = (const float*)d_in[9];
    const float* lnw1   = (const float*)d_in[10];
    const float* lnb1   = (const float*)d_in[11];
    float* out = (float*)d_out;

    __nv_bfloat16 *xh, *xl, *qh, *ql, *ph, *pl, *xsh, *xsl, *kvh, *kvl, *aoh, *aol;
    __nv_bfloat16 *wqh, *wql, *wkvh, *wkvl, *wprh, *wprl, *wsrh, *wsrl;
    float* xsf;
    cudaGetSymbolAddress((void**)&xh,   g_xh);   cudaGetSymbolAddress((void**)&xl,   g_xl);
    cudaGetSymbolAddress((void**)&qh,   g_qh);   cudaGetSymbolAddress((void**)&ql,   g_ql);
    cudaGetSymbolAddress((void**)&ph,   g_ph);   cudaGetSymbolAddress((void**)&pl,   g_pl);
    cudaGetSymbolAddress((void**)&xsf,  g_xsf);
    cudaGetSymbolAddress((void**)&xsh,  g_xsh);  cudaGetSymbolAddress((void**)&xsl,  g_xsl);
    cudaGetSymbolAddress((void**)&kvh,  g_kvh);  cudaGetSymbolAddress((void**)&kvl,  g_kvl);
    cudaGetSymbolAddress((void**)&aoh,  g_aoh);  cudaGetSymbolAddress((void**)&aol,  g_aol);
    cudaGetSymbolAddress((void**)&wqh,  g_wqh);  cudaGetSymbolAddress((void**)&wql,  g_wql);
    cudaGetSymbolAddress((void**)&wkvh, g_wkvh); cudaGetSymbolAddress((void**)&wkvl, g_wkvl);
    cudaGetSymbolAddress((void**)&wprh, g_wprh); cudaGetSymbolAddress((void**)&wprl, g_wprl);
    cudaGetSymbolAddress((void**)&wsrh, g_wsrh); cudaGetSymbolAddress((void**)&wsrl, g_wsrl);

    cudaFuncSetAttribute(gemm_s,
                         cudaFuncAttributeMaxDynamicSharedMemorySize, GSMEM_BYTES);

    const int    nX  = B_ * N_ * C_;          // per-stream activation elems
    const size_t sQ  = (size_t)nX;
    const size_t sP  = (size_t)B_ * M_ * 4 * C_;
    const size_t sXS = (size_t)B_ * M_ * C_;
    const size_t sKV = (size_t)B_ * M_ * 2 * C_;
    const float  scale = 0.17677669529663687f;   // 32^-0.5

    // pre-split inputs + weights
    split_k<<<nX / 1024, 256>>>(xh,      xl,      x0,    nX, 1.f);
    split_k<<<nX / 1024, 256>>>(xh + nX, xl + nX, x1,    nX, 1.f);
    split_k<<<(C_ * C_) / 1024, 256>>>(wqh,  wql,  Wq,    C_ * C_, 1.f);
    split_k<<<(2 * C_ * C_) / 1024, 256>>>(wkvh, wkvl, Wkv, 2 * C_ * C_, 1.f);
    split_k<<<(C_ * C_) / 1024, 256>>>(wprh, wprl, Wproj, C_ * C_, 1.f);
    split_k<<<(4 * C_ * C_) / 1024, 256>>>(wsrh, wsrl, Wsr, 4 * C_ * C_, 1.f);

    // q = scale * (x @ Wq^T) -> split
    gemm_s<<<dim3(C_ / 64, (B_ * N_) / 128, 2), 256, GSMEM_BYTES>>>(
        nullptr, qh, ql, xh, xl, wqh, wql, nullptr, C_, C_, sQ, sQ, scale, 1);
    // im2col -> split patches
    im2col_k<<<dim3((B_ * M_ * C_ + 255) / 256, 2), 256>>>(ph, pl, x0, x1);
    // xs = patches @ Wsr^T + bsr -> f32
    gemm_s<<<dim3(C_ / 64, (B_ * M_) / 128, 2), 256, GSMEM_BYTES>>>(
        xsf, nullptr, nullptr, ph, pl, wsrh, wsrl, bsr, C_, 4 * C_, sP, sXS, 1.f, 0);
    // layernorm -> split
    layernorm_k<<<dim3(B_ * M_, 2), 256>>>(xsf, xsh, xsl, lnw0, lnb0, lnw1, lnb1);
    // kv = xs @ Wkv^T -> split
    gemm_s<<<dim3((2 * C_) / 64, (B_ * M_) / 128, 2), 256, GSMEM_BYTES>>>(
        nullptr, kvh, kvl, xsh, xsl, wkvh, wkvl, nullptr, 2 * C_, C_, sXS, sKV, 1.f, 1);
    // fused attention -> split ao
    attention_k<<<dim3(N_ / 128, B_ * H_, 2), 256>>>(aoh, aol, qh, ql, kvh, kvl);
    // y = ao @ Wproj^T + bproj -> f32 output
    gemm_s<<<dim3(C_ / 64, (B_ * N_) / 128, 2), 256, GSMEM_BYTES>>>(
        out, nullptr, nullptr, aoh, aol, wprh, wprl, bproj, C_, C_, sQ, sQ, 1.f, 0);
}

// round 8
// speedup vs baseline: 6.5393x; 1.0381x over previous
#include <cuda_runtime.h>
#include <cuda_bf16.h>
#include <math.h>
#include <cstdint>

// Problem constants
#define B_    2
#define N_    4096
#define C_    256
#define H_    8        // heads
#define D_    32       // head dim
#define M_    1024     // reduced tokens (32x32)
#define HW_   64       // spatial H=W

typedef unsigned long long u64;

// ---------------- warp-level bf16 MMA (m16n8k16) ----------------
__device__ __forceinline__ void mma16816(float* d, const uint32_t* a,
                                         const uint32_t* b) {
    asm volatile(
        "mma.sync.aligned.m16n8k16.row.col.f32.bf16.bf16.f32 "
        "{%0,%1,%2,%3}, {%4,%5,%6,%7}, {%8,%9}, {%0,%1,%2,%3};"
        : "+f"(d[0]), "+f"(d[1]), "+f"(d[2]), "+f"(d[3])
        : "r"(a[0]), "r"(a[1]), "r"(a[2]), "r"(a[3]), "r"(b[0]), "r"(b[1]));
}

// split pack: hi = bf16x2(x,y), lo = bf16x2(residuals)
__device__ __forceinline__ void pk_hl(float x, float y, uint32_t& hi, uint32_t& lo) {
    __nv_bfloat16 hx = __float2bfloat16_rn(x), hy = __float2bfloat16_rn(y);
    __nv_bfloat162 H; H.x = hx; H.y = hy;
    __nv_bfloat162 L;
    L.x = __float2bfloat16_rn(x - __bfloat162float(hx));
    L.y = __float2bfloat16_rn(y - __bfloat162float(hy));
    hi = *(uint32_t*)&H;
    lo = *(uint32_t*)&L;
}
__device__ __forceinline__ void st_split(__nv_bfloat16* H, __nv_bfloat16* L,
                                         size_t off, float x, float y) {
    uint32_t h, l;
    pk_hl(x, y, h, l);
    *(uint32_t*)&H[off] = h;
    *(uint32_t*)&L[off] = l;
}

// ---------------- scratch (device globals; both streams) ----------------
__device__ __nv_bfloat16 g_xh [2*B_*N_*C_],   g_xl [2*B_*N_*C_];
__device__ __nv_bfloat16 g_qh [2*B_*N_*C_],   g_ql [2*B_*N_*C_];     // pre-scaled
__device__ float         g_xsf[2*B_*M_*C_];
__device__ __nv_bfloat16 g_xsh[2*B_*M_*C_],   g_xsl[2*B_*M_*C_];
__device__ __nv_bfloat16 g_kvh[2*B_*M_*2*C_], g_kvl[2*B_*M_*2*C_];
__device__ __nv_bfloat16 g_aoh[2*B_*N_*C_],   g_aol[2*B_*N_*C_];
__device__ __nv_bfloat16 g_wqh [C_*C_],   g_wql [C_*C_];
__device__ __nv_bfloat16 g_wkvh[2*C_*C_], g_wkvl[2*C_*C_];
__device__ __nv_bfloat16 g_wprh[C_*C_],   g_wprl[C_*C_];
__device__ __nv_bfloat16 g_wsrh[4*C_*C_], g_wsrl[4*C_*C_];

__device__ __forceinline__ void split4(__nv_bfloat16* H, __nv_bfloat16* L,
                                       const float* S, size_t i) {
    float4 v = *(const float4*)&S[i];
    uint32_t h0, l0, h1, l1;
    pk_hl(v.x, v.y, h0, l0);
    pk_hl(v.z, v.w, h1, l1);
    *(uint32_t*)&H[i]     = h0; *(uint32_t*)&H[i + 2] = h1;
    *(uint32_t*)&L[i]     = l0; *(uint32_t*)&L[i + 2] = l1;
}

// ---------------- merged splits ----------------
#define NX (B_*N_*C_)     // 2M elems per stream
__global__ __launch_bounds__(256)
void split_x(__nv_bfloat16* __restrict__ H, __nv_bfloat16* __restrict__ L,
             const float* __restrict__ x0, const float* __restrict__ x1) {
    int bx = blockIdx.x;            // 4096 blocks, 1024 elems each
    size_t i = (size_t)(bx & 2047) * 1024 + threadIdx.x * 4;
    if (bx < 2048) split4(H, L, x0, i);
    else           split4(H + NX, L + NX, x1, i);
}

__global__ __launch_bounds__(256)
void split_w(__nv_bfloat16* __restrict__ wqh,  __nv_bfloat16* __restrict__ wql,
             __nv_bfloat16* __restrict__ wkvh, __nv_bfloat16* __restrict__ wkvl,
             __nv_bfloat16* __restrict__ wprh, __nv_bfloat16* __restrict__ wprl,
             __nv_bfloat16* __restrict__ wsrh, __nv_bfloat16* __restrict__ wsrl,
             const float* __restrict__ Wq, const float* __restrict__ Wkv,
             const float* __restrict__ Wpr, const float* __restrict__ Wsr) {
    int bx = blockIdx.x;            // 512 blocks
    if (bx < 64) {
        size_t i = (size_t)bx * 1024 + threadIdx.x * 4;
        split4(wqh, wql, Wq, i);
    } else if (bx < 192) {
        size_t i = (size_t)(bx - 64) * 1024 + threadIdx.x * 4;
        split4(wkvh, wkvl, Wkv, i);
    } else if (bx < 256) {
        size_t i = (size_t)(bx - 192) * 1024 + threadIdx.x * 4;
        split4(wprh, wprl, Wpr, i);
    } else {
        size_t i = (size_t)(bx - 256) * 1024 + threadIdx.x * 4;
        split4(wsrh, wsrl, Wsr, i);
    }
}

// ================= GEMM core pieces =================
#define GSTR 72
#define GSMEM_ELEMS (2 * 128 * GSTR + 2 * 64 * GSTR)
#define GSMEM_BYTES (GSMEM_ELEMS * 2)

// ---- fused q-proj + SR-conv GEMM, 1D grid of 640 blocks ----
// bx <  128 : SR task (K=1024, A = im2col gather from xh/xl, out f32 xsf+bsr)
// bx >= 128 : Q  task (K=256,  A = xh/xl copy, out split qh/ql * scale)
__global__ __launch_bounds__(256)
void gemm_qsr(const __nv_bfloat16* __restrict__ xh, const __nv_bfloat16* __restrict__ xl,
              const __nv_bfloat16* __restrict__ wqh, const __nv_bfloat16* __restrict__ wql,
              const __nv_bfloat16* __restrict__ wsrh, const __nv_bfloat16* __restrict__ wsrl,
              __nv_bfloat16* __restrict__ qhO, __nv_bfloat16* __restrict__ qlO,
              float* __restrict__ xsf, const float* __restrict__ bsr) {
    extern __shared__ __nv_bfloat16 sm[];
    __nv_bfloat16* sAh = sm;
    __nv_bfloat16* sAl = sm + 128 * GSTR;
    __nv_bfloat16* sBh = sm + 2 * 128 * GSTR;
    __nv_bfloat16* sBl = sm + 2 * 128 * GSTR + 64 * GSTR;

    const int bx = blockIdx.x;
    const bool issr = bx < 128;
    int z, i0, j0, K;
    const __nv_bfloat16 *Bh, *Bl;
    if (issr) {
        int tb = bx;               // 128 = 2z * 16y * 4x
        z = tb >> 6;
        int r = tb & 63;
        i0 = (r >> 2) * 128; j0 = (r & 3) * 64;
        K = 1024; Bh = wsrh; Bl = wsrl;
    } else {
        int tb = bx - 128;         // 512 = 2z * 64y * 4x
        z = tb >> 8;
        int r = tb & 255;
        i0 = (r >> 2) * 128; j0 = (r & 3) * 64;
        K = 256; Bh = wqh; Bl = wql;
    }
    const __nv_bfloat16* Axh = xh + (size_t)z * NX;
    const __nv_bfloat16* Axl = xl + (size_t)z * NX;

    const int tid = threadIdx.x, wid = tid >> 5, lane = tid & 31;
    const int wm = wid & 3, wn = wid >> 2;
    const int fr = lane >> 2, fc = lane & 3;

    float acc[2][4][4] = {};

    for (int k0 = 0; k0 < K; k0 += 64) {
        if (!issr) {
            // plain copy A: rows are tokens, K=256 contiguous
#pragma unroll
            for (int r = 0; r < 4; r++) {
                int f = tid + 256 * r;
                int row = f >> 3, kq = (f & 7) << 3;
                size_t ga = (size_t)(i0 + row) * C_ + k0 + kq;
                *(uint4*)&sAh[row * GSTR + kq] = *(const uint4*)&Axh[ga];
                *(uint4*)&sAl[row * GSTR + kq] = *(const uint4*)&Axl[ga];
            }
        } else {
            // im2col gather: k = cin*4 + kh*2 + kw ; chunk covers cins cin0..cin0+15
            const int cin0 = k0 >> 2;
#pragma unroll
            for (int it = 0; it < 2; it++) {
                int f = tid + 256 * it;          // 512 tasks
                int row = f >> 2;                // 0..127
                int qp  = (f >> 1) & 1;          // kh
                int hh  = f & 1;                 // which 8-cin half
                int t = i0 + row;
                int b = t >> 10, m = t & 1023;
                int i = m >> 5, j = m & 31;
                int n0 = (2 * i + qp) * HW_ + 2 * j;   // kw=0 ; kw=1 is n0+1
                size_t base0 = ((size_t)b * N_ + n0) * C_ + cin0 + hh * 8;
                uint4 h0 = *(const uint4*)&Axh[base0];
                uint4 h1 = *(const uint4*)&Axh[base0 + C_];
                uint4 l0 = *(const uint4*)&Axl[base0];
                uint4 l1 = *(const uint4*)&Axl[base0 + C_];
                const unsigned short* H0 = (const unsigned short*)&h0;
                const unsigned short* H1 = (const unsigned short*)&h1;
                const unsigned short* L0 = (const unsigned short*)&l0;
                const unsigned short* L1 = (const unsigned short*)&l1;
                int sb = row * GSTR + hh * 32 + qp * 2;   // kk = (hh*8+c)*4 + 2*qp
#pragma unroll
                for (int c = 0; c < 8; c++) {
                    *(uint32_t*)&sAh[sb + c * 4] =
                        (uint32_t)H0[c] | ((uint32_t)H1[c] << 16);
                    *(uint32_t*)&sAl[sb + c * 4] =
                        (uint32_t)L0[c] | ((uint32_t)L1[c] << 16);
                }
            }
        }
        // B tiles: 64 x 64
#pragma unroll
        for (int r = 0; r < 2; r++) {
            int f = tid + 256 * r;
            int row = f >> 3, kq = (f & 7) << 3;
            size_t gb = (size_t)(j0 + row) * K + k0 + kq;
            *(uint4*)&sBh[row * GSTR + kq] = *(const uint4*)&Bh[gb];
            *(uint4*)&sBl[row * GSTR + kq] = *(const uint4*)&Bl[gb];
        }
        __syncthreads();

#pragma unroll
        for (int ks = 0; ks < 4; ks++) {
            const int kb = ks * 16 + fc * 2;
            uint32_t Ahf[2][4], Alf[2][4], Bhf[4][2], Blf[4][2];
#pragma unroll
            for (int mt = 0; mt < 2; mt++) {
                int rbase = (wm * 32 + mt * 16 + fr) * GSTR + kb;
                Ahf[mt][0] = *(const uint32_t*)&sAh[rbase];
                Ahf[mt][1] = *(const uint32_t*)&sAh[rbase + 8 * GSTR];
                Ahf[mt][2] = *(const uint32_t*)&sAh[rbase + 8];
                Ahf[mt][3] = *(const uint32_t*)&sAh[rbase + 8 * GSTR + 8];
                Alf[mt][0] = *(const uint32_t*)&sAl[rbase];
                Alf[mt][1] = *(const uint32_t*)&sAl[rbase + 8 * GSTR];
                Alf[mt][2] = *(const uint32_t*)&sAl[rbase + 8];
                Alf[mt][3] = *(const uint32_t*)&sAl[rbase + 8 * GSTR + 8];
            }
#pragma unroll
            for (int nt = 0; nt < 4; nt++) {
                int rbase = (wn * 32 + nt * 8 + fr) * GSTR + kb;
                Bhf[nt][0] = *(const uint32_t*)&sBh[rbase];
                Bhf[nt][1] = *(const uint32_t*)&sBh[rbase + 8];
                Blf[nt][0] = *(const uint32_t*)&sBl[rbase];
                Blf[nt][1] = *(const uint32_t*)&sBl[rbase + 8];
            }
#pragma unroll
            for (int mt = 0; mt < 2; mt++)
#pragma unroll
                for (int nt = 0; nt < 4; nt++) {
                    mma16816(acc[mt][nt], Ahf[mt], Bhf[nt]);
                    mma16816(acc[mt][nt], Ahf[mt], Blf[nt]);
                    mma16816(acc[mt][nt], Alf[mt], Bhf[nt]);
                }
        }
        __syncthreads();
    }

    if (issr) {
        float* out = xsf + (size_t)z * (B_ * M_ * C_);
#pragma unroll
        for (int mt = 0; mt < 2; mt++)
#pragma unroll
            for (int nt = 0; nt < 4; nt++) {
                int col = j0 + wn * 32 + nt * 8 + fc * 2;
                float bxv = bsr[col], byv = bsr[col + 1];
                int row0 = i0 + wm * 32 + mt * 16 + fr;
                *(float2*)&out[(size_t)row0 * C_ + col] =
                    make_float2(acc[mt][nt][0] + bxv, acc[mt][nt][1] + byv);
                *(float2*)&out[(size_t)(row0 + 8) * C_ + col] =
                    make_float2(acc[mt][nt][2] + bxv, acc[mt][nt][3] + byv);
            }
    } else {
        const float sc = 0.17677669529663687f;
        __nv_bfloat16* oh = qhO + (size_t)z * NX;
        __nv_bfloat16* ol = qlO + (size_t)z * NX;
#pragma unroll
        for (int mt = 0; mt < 2; mt++)
#pragma unroll
            for (int nt = 0; nt < 4; nt++) {
                int col = j0 + wn * 32 + nt * 8 + fc * 2;
                int row0 = i0 + wm * 32 + mt * 16 + fr;
                st_split(oh, ol, (size_t)row0 * C_ + col,
                         acc[mt][nt][0] * sc, acc[mt][nt][1] * sc);
                st_split(oh, ol, (size_t)(row0 + 8) * C_ + col,
                         acc[mt][nt][2] * sc, acc[mt][nt][3] * sc);
            }
    }
}

// ---- generic GEMM (kv + proj), pre-split inputs ----
__global__ __launch_bounds__(256)
void gemm_s(float* __restrict__ outf,
            __nv_bfloat16* __restrict__ outh, __nv_bfloat16* __restrict__ outl,
            const __nv_bfloat16* __restrict__ Ah, const __nv_bfloat16* __restrict__ Al,
            const __nv_bfloat16* __restrict__ Bh, const __nv_bfloat16* __restrict__ Bl,
            const float* __restrict__ bias, int Nc, int K,
            size_t strA, size_t strO, int splitout) {
    extern __shared__ __nv_bfloat16 sm[];
    __nv_bfloat16* sAh = sm;
    __nv_bfloat16* sAl = sm + 128 * GSTR;
    __nv_bfloat16* sBh = sm + 2 * 128 * GSTR;
    __nv_bfloat16* sBl = sm + 2 * 128 * GSTR + 64 * GSTR;

    const int z = blockIdx.z;
    Ah += z * strA; Al += z * strA;
    const int tid = threadIdx.x, wid = tid >> 5, lane = tid & 31;
    const int wm = wid & 3, wn = wid >> 2;
    const int fr = lane >> 2, fc = lane & 3;
    const int i0 = blockIdx.y * 128, j0 = blockIdx.x * 64;

    float acc[2][4][4] = {};

    for (int k0 = 0; k0 < K; k0 += 64) {
#pragma unroll
        for (int r = 0; r < 4; r++) {
            int f = tid + 256 * r;
            int row = f >> 3, kq = (f & 7) << 3;
            size_t ga = (size_t)(i0 + row) * K + k0 + kq;
            *(uint4*)&sAh[row * GSTR + kq] = *(const uint4*)&Ah[ga];
            *(uint4*)&sAl[row * GSTR + kq] = *(const uint4*)&Al[ga];
        }
#pragma unroll
        for (int r = 0; r < 2; r++) {
            int f = tid + 256 * r;
            int row = f >> 3, kq = (f & 7) << 3;
            size_t gb = (size_t)(j0 + row) * K + k0 + kq;
            *(uint4*)&sBh[row * GSTR + kq] = *(const uint4*)&Bh[gb];
            *(uint4*)&sBl[row * GSTR + kq] = *(const uint4*)&Bl[gb];
        }
        __syncthreads();

#pragma unroll
        for (int ks = 0; ks < 4; ks++) {
            const int kb = ks * 16 + fc * 2;
            uint32_t Ahf[2][4], Alf[2][4], Bhf[4][2], Blf[4][2];
#pragma unroll
            for (int mt = 0; mt < 2; mt++) {
                int rbase = (wm * 32 + mt * 16 + fr) * GSTR + kb;
                Ahf[mt][0] = *(const uint32_t*)&sAh[rbase];
                Ahf[mt][1] = *(const uint32_t*)&sAh[rbase + 8 * GSTR];
                Ahf[mt][2] = *(const uint32_t*)&sAh[rbase + 8];
                Ahf[mt][3] = *(const uint32_t*)&sAh[rbase + 8 * GSTR + 8];
                Alf[mt][0] = *(const uint32_t*)&sAl[rbase];
                Alf[mt][1] = *(const uint32_t*)&sAl[rbase + 8 * GSTR];
                Alf[mt][2] = *(const uint32_t*)&sAl[rbase + 8];
                Alf[mt][3] = *(const uint32_t*)&sAl[rbase + 8 * GSTR + 8];
            }
#pragma unroll
            for (int nt = 0; nt < 4; nt++) {
                int rbase = (wn * 32 + nt * 8 + fr) * GSTR + kb;
                Bhf[nt][0] = *(const uint32_t*)&sBh[rbase];
                Bhf[nt][1] = *(const uint32_t*)&sBh[rbase + 8];
                Blf[nt][0] = *(const uint32_t*)&sBl[rbase];
                Blf[nt][1] = *(const uint32_t*)&sBl[rbase + 8];
            }
#pragma unroll
            for (int mt = 0; mt < 2; mt++)
#pragma unroll
                for (int nt = 0; nt < 4; nt++) {
                    mma16816(acc[mt][nt], Ahf[mt], Bhf[nt]);
                    mma16816(acc[mt][nt], Ahf[mt], Blf[nt]);
                    mma16816(acc[mt][nt], Alf[mt], Bhf[nt]);
                }
        }
        __syncthreads();
    }

    if (!splitout) {
        float* out = outf + z * strO;
#pragma unroll
        for (int mt = 0; mt < 2; mt++)
#pragma unroll
            for (int nt = 0; nt < 4; nt++) {
                int col = j0 + wn * 32 + nt * 8 + fc * 2;
                float bxv = 0.f, byv = 0.f;
                if (bias) { bxv = bias[col]; byv = bias[col + 1]; }
                int row0 = i0 + wm * 32 + mt * 16 + fr;
                *(float2*)&out[(size_t)row0 * Nc + col] =
                    make_float2(acc[mt][nt][0] + bxv, acc[mt][nt][1] + byv);
                *(float2*)&out[(size_t)(row0 + 8) * Nc + col] =
                    make_float2(acc[mt][nt][2] + bxv, acc[mt][nt][3] + byv);
            }
    } else {
        __nv_bfloat16* oh = outh + z * strO;
        __nv_bfloat16* ol = outl + z * strO;
#pragma unroll
        for (int mt = 0; mt < 2; mt++)
#pragma unroll
            for (int nt = 0; nt < 4; nt++) {
                int col = j0 + wn * 32 + nt * 8 + fc * 2;
                int row0 = i0 + wm * 32 + mt * 16 + fr;
                st_split(oh, ol, (size_t)row0 * Nc + col,
                         acc[mt][nt][0], acc[mt][nt][1]);
                st_split(oh, ol, (size_t)(row0 + 8) * Nc + col,
                         acc[mt][nt][2], acc[mt][nt][3]);
            }
    }
}

// ---------------- LayerNorm over C=256, split bf16 out ----------------
__global__ __launch_bounds__(256)
void layernorm_k(const float* __restrict__ xsf,
                 __nv_bfloat16* __restrict__ xsh, __nv_bfloat16* __restrict__ xsl,
                 const float* __restrict__ w0, const float* __restrict__ b0,
                 const float* __restrict__ w1, const float* __restrict__ b1) {
    int z = blockIdx.y;
    size_t zoff = (size_t)z * B_ * M_ * C_;
    const float* w = z ? w1 : w0;
    const float* bv = z ? b1 : b0;
    int row = blockIdx.x;
    int tid = threadIdx.x;
    float v = xsf[zoff + (size_t)row * C_ + tid];
    float s = v, s2 = v * v;
#pragma unroll
    for (int o = 16; o > 0; o >>= 1) {
        s  += __shfl_xor_sync(~0u, s,  o);
        s2 += __shfl_xor_sync(~0u, s2, o);
    }
    __shared__ float rs[8], rs2[8];
    int wid = tid >> 5, lane = tid & 31;
    if (lane == 0) { rs[wid] = s; rs2[wid] = s2; }
    __syncthreads();
    float tot = 0.f, tot2 = 0.f;
#pragma unroll
    for (int i = 0; i < 8; i++) { tot += rs[i]; tot2 += rs2[i]; }
    float mu  = tot * (1.f / C_);
    float var = tot2 * (1.f / C_) - mu * mu;
    float inv = rsqrtf(var + 1e-5f);
    float y = (v - mu) * inv * w[tid] + bv[tid];
    __nv_bfloat16 hb = __float2bfloat16_rn(y);
    size_t o = zoff + (size_t)row * C_ + tid;
    xsh[o] = hb;
    xsl[o] = __float2bfloat16_rn(y - __bfloat162float(hb));
}

// ================ HMMA fused flash attention (pre-split inputs) ================
#define ASTR 40
#define VSTR 72
__global__ __launch_bounds__(256)
void attention_k(__nv_bfloat16* __restrict__ aohB, __nv_bfloat16* __restrict__ aolB,
                 const __nv_bfloat16* __restrict__ qhB, const __nv_bfloat16* __restrict__ qlB,
                 const __nv_bfloat16* __restrict__ kvhB, const __nv_bfloat16* __restrict__ kvlB) {
    __shared__ __nv_bfloat16 qh[128][ASTR], ql[128][ASTR];
    __shared__ __nv_bfloat16 kh[64][ASTR],  kl[64][ASTR];
    __shared__ __nv_bfloat16 vhT[32][VSTR], vlT[32][VSTR];

    const int z = blockIdx.z;
    const size_t sQ  = (size_t)B_ * N_ * C_;
    const size_t sKV = (size_t)B_ * M_ * 2 * C_;
    const __nv_bfloat16* qgh = qhB + z * sQ;
    const __nv_bfloat16* qgl = qlB + z * sQ;
    const __nv_bfloat16* kvh = kvhB + z * sKV;
    const __nv_bfloat16* kvl = kvlB + z * sKV;
    __nv_bfloat16* aoh = aohB + z * sQ;
    __nv_bfloat16* aol = aolB + z * sQ;
    const int tid = threadIdx.x, wid = tid >> 5, lane = tid & 31;
    const int fr = lane >> 2, fc = lane & 3;
    const int bh = blockIdx.y;
    const int b = bh >> 3, h = bh & 7;
    const int r0 = blockIdx.x * 128;

    const size_t qbase = ((size_t)b * N_ + r0) * C_ + h * D_;
#pragma unroll
    for (int r = 0; r < 2; r++) {
        int idx = tid + 256 * r;
        int row = idx >> 2, kq = (idx & 3) << 3;
        *(uint4*)&qh[row][kq] = *(const uint4*)&qgh[qbase + (size_t)row * C_ + kq];
        *(uint4*)&ql[row][kq] = *(const uint4*)&qgl[qbase + (size_t)row * C_ + kq];
    }

    float m0 = -1e30f, m1 = -1e30f, l0 = 0.f, l1 = 0.f;
    float O[4][4] = {};
    const size_t kbase = (size_t)b * M_ * (2 * C_) + h * D_;

    for (int j0 = 0; j0 < M_; j0 += 64) {
        __syncthreads();
        {
            int j = tid >> 2, kq = (tid & 3) << 3;
            size_t ga = kbase + (size_t)(j0 + j) * (2 * C_) + kq;
            *(uint4*)&kh[j][kq] = *(const uint4*)&kvh[ga];
            *(uint4*)&kl[j][kq] = *(const uint4*)&kvl[ga];
        }
        {
            int jp = tid >> 3, dq = (tid & 7) << 2;
            size_t ga = kbase + (size_t)(j0 + 2 * jp) * (2 * C_) + C_ + dq;
            uint2 ah = *(const uint2*)&kvh[ga];
            uint2 ch = *(const uint2*)&kvh[ga + 2 * C_];
            uint2 al = *(const uint2*)&kvl[ga];
            uint2 cl = *(const uint2*)&kvl[ga + 2 * C_];
            *(uint32_t*)&vhT[dq + 0][2 * jp] = __byte_perm(ah.x, ch.x, 0x5410);
            *(uint32_t*)&vhT[dq + 1][2 * jp] = __byte_perm(ah.x, ch.x, 0x7632);
            *(uint32_t*)&vhT[dq + 2][2 * jp] = __byte_perm(ah.y, ch.y, 0x5410);
            *(uint32_t*)&vhT[dq + 3][2 * jp] = __byte_perm(ah.y, ch.y, 0x7632);
            *(uint32_t*)&vlT[dq + 0][2 * jp] = __byte_perm(al.x, cl.x, 0x5410);
            *(uint32_t*)&vlT[dq + 1][2 * jp] = __byte_perm(al.x, cl.x, 0x7632);
            *(uint32_t*)&vlT[dq + 2][2 * jp] = __byte_perm(al.y, cl.y, 0x5410);
            *(uint32_t*)&vlT[dq + 3][2 * jp] = __byte_perm(al.y, cl.y, 0x7632);
        }
        __syncthreads();

        float S[8][4] = {};
        const int arow = (wid << 4) + fr;
#pragma unroll
        for (int s = 0; s < 2; s++) {
            const int kb = (s << 4) + (fc << 1);
            uint32_t Ah[4], Al[4];
            Ah[0] = *(const uint32_t*)&qh[arow][kb];
            Ah[1] = *(const uint32_t*)&qh[arow + 8][kb];
            Ah[2] = *(const uint32_t*)&qh[arow][kb + 8];
            Ah[3] = *(const uint32_t*)&qh[arow + 8][kb + 8];
            Al[0] = *(const uint32_t*)&ql[arow][kb];
            Al[1] = *(const uint32_t*)&ql[arow + 8][kb];
            Al[2] = *(const uint32_t*)&ql[arow][kb + 8];
            Al[3] = *(const uint32_t*)&ql[arow + 8][kb + 8];
#pragma unroll
            for (int t = 0; t < 8; t++) {
                const int brow = (t << 3) + fr;
                uint32_t Bh[2], Bl[2];
                Bh[0] = *(const uint32_t*)&kh[brow][kb];
                Bh[1] = *(const uint32_t*)&kh[brow][kb + 8];
                Bl[0] = *(const uint32_t*)&kl[brow][kb];
                Bl[1] = *(const uint32_t*)&kl[brow][kb + 8];
                mma16816(S[t], Ah, Bh);
                mma16816(S[t], Ah, Bl);
                mma16816(S[t], Al, Bh);
            }
        }

        float cm0 = -1e30f, cm1 = -1e30f;
#pragma unroll
        for (int t = 0; t < 8; t++) {
            cm0 = fmaxf(cm0, fmaxf(S[t][0], S[t][1]));
            cm1 = fmaxf(cm1, fmaxf(S[t][2], S[t][3]));
        }
        cm0 = fmaxf(cm0, __shfl_xor_sync(~0u, cm0, 1));
        cm0 = fmaxf(cm0, __shfl_xor_sync(~0u, cm0, 2));
        cm1 = fmaxf(cm1, __shfl_xor_sync(~0u, cm1, 1));
        cm1 = fmaxf(cm1, __shfl_xor_sync(~0u, cm1, 2));
        float nm0 = fmaxf(m0, cm0), nm1 = fmaxf(m1, cm1);
        float corr0 = __expf(m0 - nm0), corr1 = __expf(m1 - nm1);
        m0 = nm0; m1 = nm1;
        float ps0 = 0.f, ps1 = 0.f;
#pragma unroll
        for (int t = 0; t < 8; t++) {
            S[t][0] = __expf(S[t][0] - nm0);
            S[t][1] = __expf(S[t][1] - nm0);
            S[t][2] = __expf(S[t][2] - nm1);
            S[t][3] = __expf(S[t][3] - nm1);
            ps0 += S[t][0] + S[t][1];
            ps1 += S[t][2] + S[t][3];
        }
        ps0 += __shfl_xor_sync(~0u, ps0, 1);
        ps0 += __shfl_xor_sync(~0u, ps0, 2);
        ps1 += __shfl_xor_sync(~0u, ps1, 1);
        ps1 += __shfl_xor_sync(~0u, ps1, 2);
        l0 = l0 * corr0 + ps0;
        l1 = l1 * corr1 + ps1;
#pragma unroll
        for (int u = 0; u < 4; u++) {
            O[u][0] *= corr0; O[u][1] *= corr0;
            O[u][2] *= corr1; O[u][3] *= corr1;
        }

        uint32_t Ph[4][4], Pl[4][4];
#pragma unroll
        for (int s = 0; s < 4; s++) {
            pk_hl(S[2 * s][0],     S[2 * s][1],     Ph[s][0], Pl[s][0]);
            pk_hl(S[2 * s][2],     S[2 * s][3],     Ph[s][1], Pl[s][1]);
            pk_hl(S[2 * s + 1][0], S[2 * s + 1][1], Ph[s][2], Pl[s][2]);
            pk_hl(S[2 * s + 1][2], S[2 * s + 1][3], Ph[s][3], Pl[s][3]);
        }

#pragma unroll
        for (int s = 0; s < 4; s++) {
            const int jb = (s << 4) + (fc << 1);
#pragma unroll
            for (int u = 0; u < 4; u++) {
                const int dn = (u << 3) + fr;
                uint32_t Bh[2], Bl[2];
                Bh[0] = *(const uint32_t*)&vhT[dn][jb];
                Bh[1] = *(const uint32_t*)&vhT[dn][jb + 8];
                Bl[0] = *(const uint32_t*)&vlT[dn][jb];
                Bl[1] = *(const uint32_t*)&vlT[dn][jb + 8];
                mma16816(O[u], Ph[s], Bh);
                mma16816(O[u], Ph[s], Bl);
                mma16816(O[u], Pl[s], Bh);
            }
        }
    }

    const float inv0 = 1.f / l0, inv1 = 1.f / l1;
    const size_t obase = ((size_t)b * N_ + r0) * C_ + h * D_;
    const int grow = (wid << 4) + fr;
#pragma unroll
    for (int u = 0; u < 4; u++) {
        int col = (u << 3) + (fc << 1);
        st_split(aoh, aol, obase + (size_t)grow * C_ + col,
                 O[u][0] * inv0, O[u][1] * inv0);
        st_split(aoh, aol, obase + (size_t)(grow + 8) * C_ + col,
                 O[u][2] * inv1, O[u][3] * inv1);
    }
}

// ---------------- launch ----------------
extern "C" void kernel_launch(void* const* d_in, const int* in_sizes, int n_in,
                              void* d_out, int out_size) {
    const float* x0     = (const float*)d_in[0];
    const float* x1     = (const float*)d_in[1];
    const float* Wq     = (const float*)d_in[2];
    const float* Wkv    = (const float*)d_in[3];
    const float* Wproj  = (const float*)d_in[4];
    const float* bproj  = (const float*)d_in[5];
    const float* Wsr    = (const float*)d_in[6];
    const float* bsr    = (const float*)d_in[7];
    const float* lnw0   = (const float*)d_in[8];
    const float* lnb0   = (const float*)d_in[9];
    const float* lnw1   = (const float*)d_in[10];
    const float* lnb1   = (const float*)d_in[11];
    float* out = (float*)d_out;

    __nv_bfloat16 *xh, *xl, *qh, *ql, *xsh, *xsl, *kvh, *kvl, *aoh, *aol;
    __nv_bfloat16 *wqh, *wql, *wkvh, *wkvl, *wprh, *wprl, *wsrh, *wsrl;
    float* xsf;
    cudaGetSymbolAddress((void**)&xh,   g_xh);   cudaGetSymbolAddress((void**)&xl,   g_xl);
    cudaGetSymbolAddress((void**)&qh,   g_qh);   cudaGetSymbolAddress((void**)&ql,   g_ql);
    cudaGetSymbolAddress((void**)&xsf,  g_xsf);
    cudaGetSymbolAddress((void**)&xsh,  g_xsh);  cudaGetSymbolAddress((void**)&xsl,  g_xsl);
    cudaGetSymbolAddress((void**)&kvh,  g_kvh);  cudaGetSymbolAddress((void**)&kvl,  g_kvl);
    cudaGetSymbolAddress((void**)&aoh,  g_aoh);  cudaGetSymbolAddress((void**)&aol,  g_aol);
    cudaGetSymbolAddress((void**)&wqh,  g_wqh);  cudaGetSymbolAddress((void**)&wql,  g_wql);
    cudaGetSymbolAddress((void**)&wkvh, g_wkvh); cudaGetSymbolAddress((void**)&wkvl, g_wkvl);
    cudaGetSymbolAddress((void**)&wprh, g_wprh); cudaGetSymbolAddress((void**)&wprl, g_wprl);
    cudaGetSymbolAddress((void**)&wsrh, g_wsrh); cudaGetSymbolAddress((void**)&wsrl, g_wsrl);

    cudaFuncSetAttribute(gemm_s,
                         cudaFuncAttributeMaxDynamicSharedMemorySize, GSMEM_BYTES);
    cudaFuncSetAttribute(gemm_qsr,
                         cudaFuncAttributeMaxDynamicSharedMemorySize, GSMEM_BYTES);

    const size_t sQ  = (size_t)NX;
    const size_t sXS = (size_t)B_ * M_ * C_;
    const size_t sKV = (size_t)B_ * M_ * 2 * C_;

    // (1) split activations, (2) split weights
    split_x<<<4096, 256>>>(xh, xl, x0, x1);
    split_w<<<512, 256>>>(wqh, wql, wkvh, wkvl, wprh, wprl, wsrh, wsrl,
                          Wq, Wkv, Wproj, Wsr);
    // (3) fused q-proj + SR-conv (im2col inline)
    gemm_qsr<<<640, 256, GSMEM_BYTES>>>(xh, xl, wqh, wql, wsrh, wsrl,
                                        qh, ql, xsf, bsr);
    // (4) layernorm -> split
    layernorm_k<<<dim3(B_ * M_, 2), 256>>>(xsf, xsh, xsl, lnw0, lnb0, lnw1, lnb1);
    // (5) kv = xs @ Wkv^T -> split
    gemm_s<<<dim3((2 * C_) / 64, (B_ * M_) / 128, 2), 256, GSMEM_BYTES>>>(
        nullptr, kvh, kvl, xsh, xsl, wkvh, wkvl, nullptr, 2 * C_, C_, sXS, sKV, 1);
    // (6) fused attention  (ncu -s 5 -c 1 captures this launch)
    attention_k<<<dim3(N_ / 128, B_ * H_, 2), 256>>>(aoh, aol, qh, ql, kvh, kvl);
    // (7) y = ao @ Wproj^T + bproj
    gemm_s<<<dim3(C_ / 64, (B_ * N_) / 128, 2), 256, GSMEM_BYTES>>>(
        out, nullptr, nullptr, aoh, aol, wprh, wprl, bproj, C_, C_, sQ, sQ, 0);
}

// round 10
// speedup vs baseline: 6.6258x; 1.0132x over previous
#include <cuda_runtime.h>
#include <cuda_bf16.h>
#include <math.h>
#include <cstdint>

// Problem constants
#define B_    2
#define N_    4096
#define C_    256
#define H_    8        // heads
#define D_    32       // head dim
#define M_    1024     // reduced tokens (32x32)
#define HW_   64       // spatial H=W

typedef unsigned long long u64;

// ---------------- warp-level bf16 MMA (m16n8k16) ----------------
__device__ __forceinline__ void mma16816(float* d, const uint32_t* a,
                                         const uint32_t* b) {
    asm volatile(
        "mma.sync.aligned.m16n8k16.row.col.f32.bf16.bf16.f32 "
        "{%0,%1,%2,%3}, {%4,%5,%6,%7}, {%8,%9}, {%0,%1,%2,%3};"
        : "+f"(d[0]), "+f"(d[1]), "+f"(d[2]), "+f"(d[3])
        : "r"(a[0]), "r"(a[1]), "r"(a[2]), "r"(a[3]), "r"(b[0]), "r"(b[1]));
}

__device__ __forceinline__ float ex2(float x) {
    float r; asm("ex2.approx.f32 %0, %1;" : "=f"(r) : "f"(x)); return r;
}

// split pack: hi = bf16x2(x,y), lo = bf16x2(residuals)
__device__ __forceinline__ void pk_hl(float x, float y, uint32_t& hi, uint32_t& lo) {
    __nv_bfloat16 hx = __float2bfloat16_rn(x), hy = __float2bfloat16_rn(y);
    __nv_bfloat162 H; H.x = hx; H.y = hy;
    __nv_bfloat162 L;
    L.x = __float2bfloat16_rn(x - __bfloat162float(hx));
    L.y = __float2bfloat16_rn(y - __bfloat162float(hy));
    hi = *(uint32_t*)&H;
    lo = *(uint32_t*)&L;
}
__device__ __forceinline__ void st_split(__nv_bfloat16* H, __nv_bfloat16* L,
                                         size_t off, float x, float y) {
    uint32_t h, l;
    pk_hl(x, y, h, l);
    *(uint32_t*)&H[off] = h;
    *(uint32_t*)&L[off] = l;
}
// convert 8 fp32 -> hi/lo planes at element offset e (4 u32 per plane)
__device__ __forceinline__ void cv8(__nv_bfloat16* Hp, __nv_bfloat16* Lp, int e,
                                    float4 v0, float4 v1) {
    uint32_t h, l;
    pk_hl(v0.x, v0.y, h, l); *(uint32_t*)&Hp[e]     = h; *(uint32_t*)&Lp[e]     = l;
    pk_hl(v0.z, v0.w, h, l); *(uint32_t*)&Hp[e + 2] = h; *(uint32_t*)&Lp[e + 2] = l;
    pk_hl(v1.x, v1.y, h, l); *(uint32_t*)&Hp[e + 4] = h; *(uint32_t*)&Lp[e + 4] = l;
    pk_hl(v1.z, v1.w, h, l); *(uint32_t*)&Hp[e + 6] = h; *(uint32_t*)&Lp[e + 6] = l;
}

// ---------------- scratch (device globals; both streams) ----------------
#define NX (B_*N_*C_)
__device__ __nv_bfloat16 g_qh [2*NX],         g_ql [2*NX];           // pre-scaled (x log2e)
__device__ float         g_xsf[2*B_*M_*C_];
__device__ __nv_bfloat16 g_xsh[2*B_*M_*C_],   g_xsl[2*B_*M_*C_];
__device__ __nv_bfloat16 g_kvh[2*B_*M_*2*C_], g_kvl[2*B_*M_*2*C_];
__device__ __nv_bfloat16 g_aoh[2*NX],         g_aol[2*NX];
__device__ __nv_bfloat16 g_wqh [C_*C_],   g_wql [C_*C_];
__device__ __nv_bfloat16 g_wkvh[2*C_*C_], g_wkvl[2*C_*C_];
__device__ __nv_bfloat16 g_wprh[C_*C_],   g_wprl[C_*C_];
__device__ __nv_bfloat16 g_wsrh[4*C_*C_], g_wsrl[4*C_*C_];

__device__ __forceinline__ void split4(__nv_bfloat16* H, __nv_bfloat16* L,
                                       const float* S, size_t i) {
    float4 v = *(const float4*)&S[i];
    uint32_t h0, l0, h1, l1;
    pk_hl(v.x, v.y, h0, l0);
    pk_hl(v.z, v.w, h1, l1);
    *(uint32_t*)&H[i]     = h0; *(uint32_t*)&H[i + 2] = h1;
    *(uint32_t*)&L[i]     = l0; *(uint32_t*)&L[i + 2] = l1;
}

// ---------------- merged weight split ----------------
__global__ __launch_bounds__(256)
void split_w(__nv_bfloat16* __restrict__ wqh,  __nv_bfloat16* __restrict__ wql,
             __nv_bfloat16* __restrict__ wkvh, __nv_bfloat16* __restrict__ wkvl,
             __nv_bfloat16* __restrict__ wprh, __nv_bfloat16* __restrict__ wprl,
             __nv_bfloat16* __restrict__ wsrh, __nv_bfloat16* __restrict__ wsrl,
             const float* __restrict__ Wq, const float* __restrict__ Wkv,
             const float* __restrict__ Wpr, const float* __restrict__ Wsr) {
    int bx = blockIdx.x;            // 512 blocks
    if (bx < 64) {
        size_t i = (size_t)bx * 1024 + threadIdx.x * 4;
        split4(wqh, wql, Wq, i);
    } else if (bx < 192) {
        size_t i = (size_t)(bx - 64) * 1024 + threadIdx.x * 4;
        split4(wkvh, wkvl, Wkv, i);
    } else if (bx < 256) {
        size_t i = (size_t)(bx - 192) * 1024 + threadIdx.x * 4;
        split4(wprh, wprl, Wpr, i);
    } else {
        size_t i = (size_t)(bx - 256) * 1024 + threadIdx.x * 4;
        split4(wsrh, wsrl, Wsr, i);
    }
}

// ================= GEMM core pieces =================
#define GSTR 72
#define GSMEM_ELEMS (2 * 128 * GSTR + 2 * 64 * GSTR)
#define GSMEM_BYTES (GSMEM_ELEMS * 2)

// ---- fused q-proj + SR-conv GEMM; A converted from fp32 x inline ----
// bx <  128 : SR task (K=1024, im2col gather, out f32 xsf + bsr)
// bx >= 128 : Q  task (K=256,  out split qh/ql * scale*log2e)
__global__ __launch_bounds__(256)
void gemm_qsr(const float* __restrict__ x0, const float* __restrict__ x1,
              const __nv_bfloat16* __restrict__ wqh, const __nv_bfloat16* __restrict__ wql,
              const __nv_bfloat16* __restrict__ wsrh, const __nv_bfloat16* __restrict__ wsrl,
              __nv_bfloat16* __restrict__ qhO, __nv_bfloat16* __restrict__ qlO,
              float* __restrict__ xsf, const float* __restrict__ bsr) {
    extern __shared__ __nv_bfloat16 sm[];
    __nv_bfloat16* sAh = sm;
    __nv_bfloat16* sAl = sm + 128 * GSTR;
    __nv_bfloat16* sBh = sm + 2 * 128 * GSTR;
    __nv_bfloat16* sBl = sm + 2 * 128 * GSTR + 64 * GSTR;

    const int bx = blockIdx.x;
    const bool issr = bx < 128;
    int z, i0, j0, K;
    const __nv_bfloat16 *Bh, *Bl;
    if (issr) {
        int tb = bx;
        z = tb >> 6;
        int r = tb & 63;
        i0 = (r >> 2) * 128; j0 = (r & 3) * 64;
        K = 1024; Bh = wsrh; Bl = wsrl;
    } else {
        int tb = bx - 128;
        z = tb >> 8;
        int r = tb & 255;
        i0 = (r >> 2) * 128; j0 = (r & 3) * 64;
        K = 256; Bh = wqh; Bl = wql;
    }
    const float* X = z ? x1 : x0;

    const int tid = threadIdx.x, wid = tid >> 5, lane = tid & 31;
    const int wm = wid & 3, wn = wid >> 2;
    const int fr = lane >> 2, fc = lane & 3;

    float acc[2][4][4] = {};

    for (int k0 = 0; k0 < K; k0 += 64) {
        if (!issr) {
            // plain A: rows are tokens, K=256 contiguous fp32 -> split inline
#pragma unroll
            for (int r = 0; r < 4; r++) {
                int f = tid + 256 * r;
                int row = f >> 3, kq = (f & 7) << 3;
                const float* ga = &X[(size_t)(i0 + row) * C_ + k0 + kq];
                float4 v0 = *(const float4*)ga;
                float4 v1 = *(const float4*)(ga + 4);
                cv8(sAh, sAl, row * GSTR + kq, v0, v1);
            }
        } else {
            // im2col gather: k = cin*4 + kh*2 + kw ; chunk covers cin0..cin0+15
            const int cin0 = k0 >> 2;
#pragma unroll
            for (int it = 0; it < 2; it++) {
                int f = tid + 256 * it;          // 512 tasks
                int row = f >> 2;                // 0..127
                int qp  = (f >> 1) & 1;          // kh
                int hh  = f & 1;                 // which 8-cin half
                int t = i0 + row;
                int b = t >> 10, m = t & 1023;
                int i = m >> 5, j = m & 31;
                int n0 = (2 * i + qp) * HW_ + 2 * j;   // kw=0 ; kw=1 at n0+1
                const float* p0 = &X[((size_t)b * N_ + n0) * C_ + cin0 + hh * 8];
                float4 a0 = *(const float4*)p0;
                float4 a1 = *(const float4*)(p0 + 4);
                float4 c0 = *(const float4*)(p0 + C_);
                float4 c1 = *(const float4*)(p0 + C_ + 4);
                float av[8] = {a0.x, a0.y, a0.z, a0.w, a1.x, a1.y, a1.z, a1.w};
                float cv[8] = {c0.x, c0.y, c0.z, c0.w, c1.x, c1.y, c1.z, c1.w};
                int sb = row * GSTR + hh * 32 + qp * 2;   // kk = (hh*8+c)*4 + 2*qp
#pragma unroll
                for (int c = 0; c < 8; c++) {
                    uint32_t h, l;
                    pk_hl(av[c], cv[c], h, l);            // (kw0, kw1) pair
                    *(uint32_t*)&sAh[sb + c * 4] = h;
                    *(uint32_t*)&sAl[sb + c * 4] = l;
                }
            }
        }
        // B tiles: 64 x 64 (pre-split)
#pragma unroll
        for (int r = 0; r < 2; r++) {
            int f = tid + 256 * r;
            int row = f >> 3, kq = (f & 7) << 3;
            size_t gb = (size_t)(j0 + row) * K + k0 + kq;
            *(uint4*)&sBh[row * GSTR + kq] = *(const uint4*)&Bh[gb];
            *(uint4*)&sBl[row * GSTR + kq] = *(const uint4*)&Bl[gb];
        }
        __syncthreads();

#pragma unroll
        for (int ks = 0; ks < 4; ks++) {
            const int kb = ks * 16 + fc * 2;
            uint32_t Ahf[2][4], Alf[2][4], Bhf[4][2], Blf[4][2];
#pragma unroll
            for (int mt = 0; mt < 2; mt++) {
                int rbase = (wm * 32 + mt * 16 + fr) * GSTR + kb;
                Ahf[mt][0] = *(const uint32_t*)&sAh[rbase];
                Ahf[mt][1] = *(const uint32_t*)&sAh[rbase + 8 * GSTR];
                Ahf[mt][2] = *(const uint32_t*)&sAh[rbase + 8];
                Ahf[mt][3] = *(const uint32_t*)&sAh[rbase + 8 * GSTR + 8];
                Alf[mt][0] = *(const uint32_t*)&sAl[rbase];
                Alf[mt][1] = *(const uint32_t*)&sAl[rbase + 8 * GSTR];
                Alf[mt][2] = *(const uint32_t*)&sAl[rbase + 8];
                Alf[mt][3] = *(const uint32_t*)&sAl[rbase + 8 * GSTR + 8];
            }
#pragma unroll
            for (int nt = 0; nt < 4; nt++) {
                int rbase = (wn * 32 + nt * 8 + fr) * GSTR + kb;
                Bhf[nt][0] = *(const uint32_t*)&sBh[rbase];
                Bhf[nt][1] = *(const uint32_t*)&sBh[rbase + 8];
                Blf[nt][0] = *(const uint32_t*)&sBl[rbase];
                Blf[nt][1] = *(const uint32_t*)&sBl[rbase + 8];
            }
#pragma unroll
            for (int mt = 0; mt < 2; mt++)
#pragma unroll
                for (int nt = 0; nt < 4; nt++) {
                    mma16816(acc[mt][nt], Ahf[mt], Bhf[nt]);
                    mma16816(acc[mt][nt], Ahf[mt], Blf[nt]);
                    mma16816(acc[mt][nt], Alf[mt], Bhf[nt]);
                }
        }
        __syncthreads();
    }

    if (issr) {
        float* out = xsf + (size_t)z * (B_ * M_ * C_);
#pragma unroll
        for (int mt = 0; mt < 2; mt++)
#pragma unroll
            for (int nt = 0; nt < 4; nt++) {
                int col = j0 + wn * 32 + nt * 8 + fc * 2;
                float bxv = bsr[col], byv = bsr[col + 1];
                int row0 = i0 + wm * 32 + mt * 16 + fr;
                *(float2*)&out[(size_t)row0 * C_ + col] =
                    make_float2(acc[mt][nt][0] + bxv, acc[mt][nt][1] + byv);
                *(float2*)&out[(size_t)(row0 + 8) * C_ + col] =
                    make_float2(acc[mt][nt][2] + bxv, acc[mt][nt][3] + byv);
            }
    } else {
        // scale * log2e folded so attention softmax can use ex2 directly
        const float sc = 0.17677669529663687f * 1.4426950408889634f;
        __nv_bfloat16* oh = qhO + (size_t)z * NX;
        __nv_bfloat16* ol = qlO + (size_t)z * NX;
#pragma unroll
        for (int mt = 0; mt < 2; mt++)
#pragma unroll
            for (int nt = 0; nt < 4; nt++) {
                int col = j0 + wn * 32 + nt * 8 + fc * 2;
                int row0 = i0 + wm * 32 + mt * 16 + fr;
                st_split(oh, ol, (size_t)row0 * C_ + col,
                         acc[mt][nt][0] * sc, acc[mt][nt][1] * sc);
                st_split(oh, ol, (size_t)(row0 + 8) * C_ + col,
                         acc[mt][nt][2] * sc, acc[mt][nt][3] * sc);
            }
    }
}

// ---- generic GEMM (kv + proj), pre-split inputs ----
__global__ __launch_bounds__(256)
void gemm_s(float* __restrict__ outf,
            __nv_bfloat16* __restrict__ outh, __nv_bfloat16* __restrict__ outl,
            const __nv_bfloat16* __restrict__ Ah, const __nv_bfloat16* __restrict__ Al,
            const __nv_bfloat16* __restrict__ Bh, const __nv_bfloat16* __restrict__ Bl,
            const float* __restrict__ bias, int Nc, int K,
            size_t strA, size_t strO, int splitout) {
    extern __shared__ __nv_bfloat16 sm[];
    __nv_bfloat16* sAh = sm;
    __nv_bfloat16* sAl = sm + 128 * GSTR;
    __nv_bfloat16* sBh = sm + 2 * 128 * GSTR;
    __nv_bfloat16* sBl = sm + 2 * 128 * GSTR + 64 * GSTR;

    const int z = blockIdx.z;
    Ah += z * strA; Al += z * strA;
    const int tid = threadIdx.x, wid = tid >> 5, lane = tid & 31;
    const int wm = wid & 3, wn = wid >> 2;
    const int fr = lane >> 2, fc = lane & 3;
    const int i0 = blockIdx.y * 128, j0 = blockIdx.x * 64;

    float acc[2][4][4] = {};

    for (int k0 = 0; k0 < K; k0 += 64) {
#pragma unroll
        for (int r = 0; r < 4; r++) {
            int f = tid + 256 * r;
            int row = f >> 3, kq = (f & 7) << 3;
            size_t ga = (size_t)(i0 + row) * K + k0 + kq;
            *(uint4*)&sAh[row * GSTR + kq] = *(const uint4*)&Ah[ga];
            *(uint4*)&sAl[row * GSTR + kq] = *(const uint4*)&Al[ga];
        }
#pragma unroll
        for (int r = 0; r < 2; r++) {
            int f = tid + 256 * r;
            int row = f >> 3, kq = (f & 7) << 3;
            size_t gb = (size_t)(j0 + row) * K + k0 + kq;
            *(uint4*)&sBh[row * GSTR + kq] = *(const uint4*)&Bh[gb];
            *(uint4*)&sBl[row * GSTR + kq] = *(const uint4*)&Bl[gb];
        }
        __syncthreads();

#pragma unroll
        for (int ks = 0; ks < 4; ks++) {
            const int kb = ks * 16 + fc * 2;
            uint32_t Ahf[2][4], Alf[2][4], Bhf[4][2], Blf[4][2];
#pragma unroll
            for (int mt = 0; mt < 2; mt++) {
                int rbase = (wm * 32 + mt * 16 + fr) * GSTR + kb;
                Ahf[mt][0] = *(const uint32_t*)&sAh[rbase];
                Ahf[mt][1] = *(const uint32_t*)&sAh[rbase + 8 * GSTR];
                Ahf[mt][2] = *(const uint32_t*)&sAh[rbase + 8];
                Ahf[mt][3] = *(const uint32_t*)&sAh[rbase + 8 * GSTR + 8];
                Alf[mt][0] = *(const uint32_t*)&sAl[rbase];
                Alf[mt][1] = *(const uint32_t*)&sAl[rbase + 8 * GSTR];
                Alf[mt][2] = *(const uint32_t*)&sAl[rbase + 8];
                Alf[mt][3] = *(const uint32_t*)&sAl[rbase + 8 * GSTR + 8];
            }
#pragma unroll
            for (int nt = 0; nt < 4; nt++) {
                int rbase = (wn * 32 + nt * 8 + fr) * GSTR + kb;
                Bhf[nt][0] = *(const uint32_t*)&sBh[rbase];
                Bhf[nt][1] = *(const uint32_t*)&sBh[rbase + 8];
                Blf[nt][0] = *(const uint32_t*)&sBl[rbase];
                Blf[nt][1] = *(const uint32_t*)&sBl[rbase + 8];
            }
#pragma unroll
            for (int mt = 0; mt < 2; mt++)
#pragma unroll
                for (int nt = 0; nt < 4; nt++) {
                    mma16816(acc[mt][nt], Ahf[mt], Bhf[nt]);
                    mma16816(acc[mt][nt], Ahf[mt], Blf[nt]);
                    mma16816(acc[mt][nt], Alf[mt], Bhf[nt]);
                }
        }
        __syncthreads();
    }

    if (!splitout) {
        float* out = outf + z * strO;
#pragma unroll
        for (int mt = 0; mt < 2; mt++)
#pragma unroll
            for (int nt = 0; nt < 4; nt++) {
                int col = j0 + wn * 32 + nt * 8 + fc * 2;
                float bxv = 0.f, byv = 0.f;
                if (bias) { bxv = bias[col]; byv = bias[col + 1]; }
                int row0 = i0 + wm * 32 + mt * 16 + fr;
                *(float2*)&out[(size_t)row0 * Nc + col] =
                    make_float2(acc[mt][nt][0] + bxv, acc[mt][nt][1] + byv);
                *(float2*)&out[(size_t)(row0 + 8) * Nc + col] =
                    make_float2(acc[mt][nt][2] + bxv, acc[mt][nt][3] + byv);
            }
    } else {
        __nv_bfloat16* oh = outh + z * strO;
        __nv_bfloat16* ol = outl + z * strO;
#pragma unroll
        for (int mt = 0; mt < 2; mt++)
#pragma unroll
            for (int nt = 0; nt < 4; nt++) {
                int col = j0 + wn * 32 + nt * 8 + fc * 2;
                int row0 = i0 + wm * 32 + mt * 16 + fr;
                st_split(oh, ol, (size_t)row0 * Nc + col,
                         acc[mt][nt][0], acc[mt][nt][1]);
                st_split(oh, ol, (size_t)(row0 + 8) * Nc + col,
                         acc[mt][nt][2], acc[mt][nt][3]);
            }
    }
}

// ---------------- LayerNorm: warp per row, float4 IO ----------------
__global__ __launch_bounds__(256)
void layernorm_k(const float* __restrict__ xsf,
                 __nv_bfloat16* __restrict__ xsh, __nv_bfloat16* __restrict__ xsl,
                 const float* __restrict__ w0, const float* __restrict__ b0,
                 const float* __restrict__ w1, const float* __restrict__ b1) {
    int z = blockIdx.y;
    size_t zoff = (size_t)z * B_ * M_ * C_;
    const float* w = z ? w1 : w0;
    const float* bv = z ? b1 : b0;
    int row = blockIdx.x * 8 + (threadIdx.x >> 5);
    int lane = threadIdx.x & 31;
    const float* src = xsf + zoff + (size_t)row * C_ + lane * 8;
    float4 a = *(const float4*)src;
    float4 c = *(const float4*)(src + 4);
    float v[8] = {a.x, a.y, a.z, a.w, c.x, c.y, c.z, c.w};
    float s = 0.f, s2 = 0.f;
#pragma unroll
    for (int i = 0; i < 8; i++) { s += v[i]; s2 += v[i] * v[i]; }
#pragma unroll
    for (int o = 16; o > 0; o >>= 1) {
        s  += __shfl_xor_sync(~0u, s,  o);
        s2 += __shfl_xor_sync(~0u, s2, o);
    }
    float mu  = s * (1.f / C_);
    float var = s2 * (1.f / C_) - mu * mu;
    float inv = rsqrtf(var + 1e-5f);
    float4 wa = *(const float4*)&w[lane * 8];
    float4 wc = *(const float4*)&w[lane * 8 + 4];
    float4 ba = *(const float4*)&bv[lane * 8];
    float4 bc = *(const float4*)&bv[lane * 8 + 4];
    float wv[8] = {wa.x, wa.y, wa.z, wa.w, wc.x, wc.y, wc.z, wc.w};
    float bb[8] = {ba.x, ba.y, ba.z, ba.w, bc.x, bc.y, bc.z, bc.w};
    size_t o = zoff + (size_t)row * C_ + lane * 8;
#pragma unroll
    for (int i = 0; i < 4; i++) {
        float y0 = (v[2 * i]     - mu) * inv * wv[2 * i]     + bb[2 * i];
        float y1 = (v[2 * i + 1] - mu) * inv * wv[2 * i + 1] + bb[2 * i + 1];
        st_split(xsh, xsl, o + 2 * i, y0, y1);
    }
}

// ================ HMMA fused flash attention (reg-prefetch pipeline) ================
#define ASTR 40
#define VSTR 72
__global__ __launch_bounds__(256, 2)
void attention_k(__nv_bfloat16* __restrict__ aohB, __nv_bfloat16* __restrict__ aolB,
                 const __nv_bfloat16* __restrict__ qhB, const __nv_bfloat16* __restrict__ qlB,
                 const __nv_bfloat16* __restrict__ kvhB, const __nv_bfloat16* __restrict__ kvlB) {
    __shared__ __nv_bfloat16 qh[128][ASTR], ql[128][ASTR];
    __shared__ __nv_bfloat16 kh[64][ASTR],  kl[64][ASTR];
    __shared__ __nv_bfloat16 vhT[32][VSTR], vlT[32][VSTR];

    const int z = blockIdx.z;
    const size_t sQ  = (size_t)B_ * N_ * C_;
    const size_t sKV = (size_t)B_ * M_ * 2 * C_;
    const __nv_bfloat16* qgh = qhB + z * sQ;
    const __nv_bfloat16* qgl = qlB + z * sQ;
    const __nv_bfloat16* kvh = kvhB + z * sKV;
    const __nv_bfloat16* kvl = kvlB + z * sKV;
    __nv_bfloat16* aoh = aohB + z * sQ;
    __nv_bfloat16* aol = aolB + z * sQ;
    const int tid = threadIdx.x, wid = tid >> 5, lane = tid & 31;
    const int fr = lane >> 2, fc = lane & 3;
    const int bh = blockIdx.y;
    const int b = bh >> 3, h = bh & 7;
    const int r0 = blockIdx.x * 128;

    const size_t qbase = ((size_t)b * N_ + r0) * C_ + h * D_;
#pragma unroll
    for (int r = 0; r < 2; r++) {
        int idx = tid + 256 * r;
        int row = idx >> 2, kq = (idx & 3) << 3;
        *(uint4*)&qh[row][kq] = *(const uint4*)&qgh[qbase + (size_t)row * C_ + kq];
        *(uint4*)&ql[row][kq] = *(const uint4*)&qgl[qbase + (size_t)row * C_ + kq];
    }

    float m0 = -1e30f, m1 = -1e30f, l0 = 0.f, l1 = 0.f;
    float O[4][4] = {};
    const size_t kbase = (size_t)b * M_ * (2 * C_) + h * D_;

    // ---- register prefetch of chunk 0 ----
    const int kj = tid >> 2, kq4 = (tid & 3) << 3;
    const int vjp = tid >> 3, vdq = (tid & 7) << 2;
    uint4 pkh, pkl;
    uint2 pah, pch, pal, pcl;
    {
        size_t ga = kbase + (size_t)kj * (2 * C_) + kq4;
        pkh = *(const uint4*)&kvh[ga];
        pkl = *(const uint4*)&kvl[ga];
        size_t gv = kbase + (size_t)(2 * vjp) * (2 * C_) + C_ + vdq;
        pah = *(const uint2*)&kvh[gv];
        pch = *(const uint2*)&kvh[gv + 2 * C_];
        pal = *(const uint2*)&kvl[gv];
        pcl = *(const uint2*)&kvl[gv + 2 * C_];
    }

    for (int j0 = 0; j0 < M_; j0 += 64) {
        __syncthreads();                       // prior chunk's compute done
        *(uint4*)&kh[kj][kq4] = pkh;
        *(uint4*)&kl[kj][kq4] = pkl;
        *(uint32_t*)&vhT[vdq + 0][2 * vjp] = __byte_perm(pah.x, pch.x, 0x5410);
        *(uint32_t*)&vhT[vdq + 1][2 * vjp] = __byte_perm(pah.x, pch.x, 0x7632);
        *(uint32_t*)&vhT[vdq + 2][2 * vjp] = __byte_perm(pah.y, pch.y, 0x5410);
        *(uint32_t*)&vhT[vdq + 3][2 * vjp] = __byte_perm(pah.y, pch.y, 0x7632);
        *(uint32_t*)&vlT[vdq + 0][2 * vjp] = __byte_perm(pal.x, pcl.x, 0x5410);
        *(uint32_t*)&vlT[vdq + 1][2 * vjp] = __byte_perm(pal.x, pcl.x, 0x7632);
        *(uint32_t*)&vlT[vdq + 2][2 * vjp] = __byte_perm(pal.y, pcl.y, 0x5410);
        *(uint32_t*)&vlT[vdq + 3][2 * vjp] = __byte_perm(pal.y, pcl.y, 0x7632);
        __syncthreads();
        if (j0 + 64 < M_) {                    // prefetch next chunk (overlaps MMAs)
            size_t ga = kbase + (size_t)(j0 + 64 + kj) * (2 * C_) + kq4;
            pkh = *(const uint4*)&kvh[ga];
            pkl = *(const uint4*)&kvl[ga];
            size_t gv = kbase + (size_t)(j0 + 64 + 2 * vjp) * (2 * C_) + C_ + vdq;
            pah = *(const uint2*)&kvh[gv];
            pch = *(const uint2*)&kvh[gv + 2 * C_];
            pal = *(const uint2*)&kvl[gv];
            pcl = *(const uint2*)&kvl[gv + 2 * C_];
        }

        // ---- S = Q K^T (logits already in log2 units) ----
        float S[8][4] = {};
        const int arow = (wid << 4) + fr;
#pragma unroll
        for (int s = 0; s < 2; s++) {
            const int kb = (s << 4) + (fc << 1);
            uint32_t Ah[4], Al[4];
            Ah[0] = *(const uint32_t*)&qh[arow][kb];
            Ah[1] = *(const uint32_t*)&qh[arow + 8][kb];
            Ah[2] = *(const uint32_t*)&qh[arow][kb + 8];
            Ah[3] = *(const uint32_t*)&qh[arow + 8][kb + 8];
            Al[0] = *(const uint32_t*)&ql[arow][kb];
            Al[1] = *(const uint32_t*)&ql[arow + 8][kb];
            Al[2] = *(const uint32_t*)&ql[arow][kb + 8];
            Al[3] = *(const uint32_t*)&ql[arow + 8][kb + 8];
#pragma unroll
            for (int t = 0; t < 8; t++) {
                const int brow = (t << 3) + fr;
                uint32_t Bh[2], Bl[2];
                Bh[0] = *(const uint32_t*)&kh[brow][kb];
                Bh[1] = *(const uint32_t*)&kh[brow][kb + 8];
                Bl[0] = *(const uint32_t*)&kl[brow][kb];
                Bl[1] = *(const uint32_t*)&kl[brow][kb + 8];
                mma16816(S[t], Ah, Bh);
                mma16816(S[t], Ah, Bl);
                mma16816(S[t], Al, Bh);
            }
        }

        // ---- online softmax (base-2) ----
        float cm0 = -1e30f, cm1 = -1e30f;
#pragma unroll
        for (int t = 0; t < 8; t++) {
            cm0 = fmaxf(cm0, fmaxf(S[t][0], S[t][1]));
            cm1 = fmaxf(cm1, fmaxf(S[t][2], S[t][3]));
        }
        cm0 = fmaxf(cm0, __shfl_xor_sync(~0u, cm0, 1));
        cm0 = fmaxf(cm0, __shfl_xor_sync(~0u, cm0, 2));
        cm1 = fmaxf(cm1, __shfl_xor_sync(~0u, cm1, 1));
        cm1 = fmaxf(cm1, __shfl_xor_sync(~0u, cm1, 2));
        float nm0 = fmaxf(m0, cm0), nm1 = fmaxf(m1, cm1);
        float corr0 = ex2(m0 - nm0), corr1 = ex2(m1 - nm1);
        m0 = nm0; m1 = nm1;
        float ps0 = 0.f, ps1 = 0.f;
#pragma unroll
        for (int t = 0; t < 8; t++) {
            S[t][0] = ex2(S[t][0] - nm0);
            S[t][1] = ex2(S[t][1] - nm0);
            S[t][2] = ex2(S[t][2] - nm1);
            S[t][3] = ex2(S[t][3] - nm1);
            ps0 += S[t][0] + S[t][1];
            ps1 += S[t][2] + S[t][3];
        }
        ps0 += __shfl_xor_sync(~0u, ps0, 1);
        ps0 += __shfl_xor_sync(~0u, ps0, 2);
        ps1 += __shfl_xor_sync(~0u, ps1, 1);
        ps1 += __shfl_xor_sync(~0u, ps1, 2);
        l0 = l0 * corr0 + ps0;
        l1 = l1 * corr1 + ps1;
#pragma unroll
        for (int u = 0; u < 4; u++) {
            O[u][0] *= corr0; O[u][1] *= corr0;
            O[u][2] *= corr1; O[u][3] *= corr1;
        }

        // ---- O += P V (P packed per s-group to cut live registers) ----
#pragma unroll
        for (int s = 0; s < 4; s++) {
            uint32_t Ph[4], Pl[4];
            pk_hl(S[2 * s][0],     S[2 * s][1],     Ph[0], Pl[0]);
            pk_hl(S[2 * s][2],     S[2 * s][3],     Ph[1], Pl[1]);
            pk_hl(S[2 * s + 1][0], S[2 * s + 1][1], Ph[2], Pl[2]);
            pk_hl(S[2 * s + 1][2], S[2 * s + 1][3], Ph[3], Pl[3]);
            const int jb = (s << 4) + (fc << 1);
#pragma unroll
            for (int u = 0; u < 4; u++) {
                const int dn = (u << 3) + fr;
                uint32_t Bh[2], Bl[2];
                Bh[0] = *(const uint32_t*)&vhT[dn][jb];
                Bh[1] = *(const uint32_t*)&vhT[dn][jb + 8];
                Bl[0] = *(const uint32_t*)&vlT[dn][jb];
                Bl[1] = *(const uint32_t*)&vlT[dn][jb + 8];
                mma16816(O[u], Ph, Bh);
                mma16816(O[u], Ph, Bl);
                mma16816(O[u], Pl, Bh);
            }
        }
    }

    const float inv0 = 1.f / l0, inv1 = 1.f / l1;
    const size_t obase = ((size_t)b * N_ + r0) * C_ + h * D_;
    const int grow = (wid << 4) + fr;
#pragma unroll
    for (int u = 0; u < 4; u++) {
        int col = (u << 3) + (fc << 1);
        st_split(aoh, aol, obase + (size_t)grow * C_ + col,
                 O[u][0] * inv0, O[u][1] * inv0);
        st_split(aoh, aol, obase + (size_t)(grow + 8) * C_ + col,
                 O[u][2] * inv1, O[u][3] * inv1);
    }
}

// ---------------- launch ----------------
extern "C" void kernel_launch(void* const* d_in, const int* in_sizes, int n_in,
                              void* d_out, int out_size) {
    const float* x0     = (const float*)d_in[0];
    const float* x1     = (const float*)d_in[1];
    const float* Wq     = (const float*)d_in[2];
    const float* Wkv    = (const float*)d_in[3];
    const float* Wproj  = (const float*)d_in[4];
    const float* bproj  = (const float*)d_in[5];
    const float* Wsr    = (const float*)d_in[6];
    const float* bsr    = (const float*)d_in[7];
    const float* lnw0   = (const float*)d_in[8];
    const float* lnb0   = (const float*)d_in[9];
    const float* lnw1   = (const float*)d_in[10];
    const float* lnb1   = (const float*)d_in[11];
    float* out = (float*)d_out;

    __nv_bfloat16 *qh, *ql, *xsh, *xsl, *kvh, *kvl, *aoh, *aol;
    __nv_bfloat16 *wqh, *wql, *wkvh, *wkvl, *wprh, *wprl, *wsrh, *wsrl;
    float* xsf;
    cudaGetSymbolAddress((void**)&qh,   g_qh);   cudaGetSymbolAddress((void**)&ql,   g_ql);
    cudaGetSymbolAddress((void**)&xsf,  g_xsf);
    cudaGetSymbolAddress((void**)&xsh,  g_xsh);  cudaGetSymbolAddress((void**)&xsl,  g_xsl);
    cudaGetSymbolAddress((void**)&kvh,  g_kvh);  cudaGetSymbolAddress((void**)&kvl,  g_kvl);
    cudaGetSymbolAddress((void**)&aoh,  g_aoh);  cudaGetSymbolAddress((void**)&aol,  g_aol);
    cudaGetSymbolAddress((void**)&wqh,  g_wqh);  cudaGetSymbolAddress((void**)&wql,  g_wql);
    cudaGetSymbolAddress((void**)&wkvh, g_wkvh); cudaGetSymbolAddress((void**)&wkvl, g_wkvl);
    cudaGetSymbolAddress((void**)&wprh, g_wprh); cudaGetSymbolAddress((void**)&wprl, g_wprl);
    cudaGetSymbolAddress((void**)&wsrh, g_wsrh); cudaGetSymbolAddress((void**)&wsrl, g_wsrl);

    cudaFuncSetAttribute(gemm_s,
                         cudaFuncAttributeMaxDynamicSharedMemorySize, GSMEM_BYTES);
    cudaFuncSetAttribute(gemm_qsr,
                         cudaFuncAttributeMaxDynamicSharedMemorySize, GSMEM_BYTES);

    const size_t sQ  = (size_t)NX;
    const size_t sXS = (size_t)B_ * M_ * C_;
    const size_t sKV = (size_t)B_ * M_ * 2 * C_;

    // (1) split weights (x is converted inline in gemm_qsr)
    split_w<<<512, 256>>>(wqh, wql, wkvh, wkvl, wprh, wprl, wsrh, wsrl,
                          Wq, Wkv, Wproj, Wsr);
    // (2) fused q-proj + SR-conv (im2col + fp32->split inline)
    gemm_qsr<<<640, 256, GSMEM_BYTES>>>(x0, x1, wqh, wql, wsrh, wsrl,
                                        qh, ql, xsf, bsr);
    // (3) layernorm -> split (warp per row)
    layernorm_k<<<dim3((B_ * M_) / 8, 2), 256>>>(xsf, xsh, xsl,
                                                 lnw0, lnb0, lnw1, lnb1);
    // (4) kv = xs @ Wkv^T -> split
    gemm_s<<<dim3((2 * C_) / 64, (B_ * M_) / 128, 2), 256, GSMEM_BYTES>>>(
        nullptr, kvh, kvl, xsh, xsl, wkvh, wkvl, nullptr, 2 * C_, C_, sXS, sKV, 1);
    // (5) fused attention (pipelined)
    attention_k<<<dim3(N_ / 128, B_ * H_, 2), 256>>>(aoh, aol, qh, ql, kvh, kvl);
    // (6) y = ao @ Wproj^T + bproj
    gemm_s<<<dim3(C_ / 64, (B_ * N_) / 128, 2), 256, GSMEM_BYTES>>>(
        out, nullptr, nullptr, aoh, aol, wprh, wprl, bproj, C_, C_, sQ, sQ, 0);
}